// round 4
// baseline (speedup 1.0000x reference)
#include <cuda_runtime.h>
#include <math.h>

// Problem constants (from reference setup_inputs)
#define BB 2
#define HH 256
#define WW 256
#define DD 128
#define D3 (DD * DD * DD)
#define DT 0.03125f
#define NSTEPS 111

// Scratch: channel-interleaved volume [B, D, D, D, 4] as float4. 64 MB.
__device__ float4 g_vol[BB * D3];

// ---------------------------------------------------------------------------
// Pass 1: interleave volume channels (vectorized: 4 voxels per thread).
// in: [B, 4, D, D, D]  out: [B, D^3] float4
// ---------------------------------------------------------------------------
__global__ void interleave_kernel(const float4* __restrict__ vol) {
    const int QP = D3 / 4;  // float4 groups per channel plane
    long i4 = (long)blockIdx.x * blockDim.x + threadIdx.x;
    if (i4 >= (long)BB * QP) return;
    int b = (int)(i4 / QP);
    int s4 = (int)(i4 % QP);
    const float4* base = vol + (long)b * 4 * QP;
    float4 c0 = __ldg(base + 0 * QP + s4);
    float4 c1 = __ldg(base + 1 * QP + s4);
    float4 c2 = __ldg(base + 2 * QP + s4);
    float4 c3 = __ldg(base + 3 * QP + s4);
    long o = (long)b * D3 + (long)s4 * 4;
    g_vol[o + 0] = make_float4(c0.x, c1.x, c2.x, c3.x);
    g_vol[o + 1] = make_float4(c0.y, c1.y, c2.y, c3.y);
    g_vol[o + 2] = make_float4(c0.z, c1.z, c2.z, c3.z);
    g_vol[o + 3] = make_float4(c0.w, c1.w, c2.w, c3.w);
}

// ---------------------------------------------------------------------------
// Pass 2: ray march, 2 steps per iteration (16 loads in flight).
// Ray setup + position stepping replicate the reference's IEEE fp32 ops
// bit-exactly (unfused _rn intrinsics): step-0 validity is a knife-edge
// (entry position lies exactly on the cube face). Everything downstream of a
// valid position is smooth, so FMA contraction there is harmless.
// ---------------------------------------------------------------------------
__global__ void __launch_bounds__(128, 6)
raymarch_kernel(const float* __restrict__ camrot,
                const float* __restrict__ campos,
                const float* __restrict__ focal,
                const float* __restrict__ princpt,
                const float* __restrict__ pixelcoords,
                float* __restrict__ out) {
    int x = blockIdx.x * blockDim.x + threadIdx.x;
    int y = blockIdx.y * blockDim.y + threadIdx.y;
    int b = blockIdx.z;

    // --- camera ray (bit-exact vs reference) ---
    long pidx = (((long)b * HH + y) * WW + x) * 2;
    float px = pixelcoords[pidx + 0];
    float py = pixelcoords[pidx + 1];
    float rx = __fdiv_rn(__fsub_rn(px, princpt[b * 2 + 0]), focal[b * 2 + 0]);
    float ry = __fdiv_rn(__fsub_rn(py, princpt[b * 2 + 1]), focal[b * 2 + 1]);
    float rz = 1.0f;
    const float* R = camrot + b * 9;  // dir_j = sum_i R[i][j] * r_i
    float dx = __fadd_rn(__fadd_rn(__fmul_rn(R[0], rx), __fmul_rn(R[3], ry)),
                         __fmul_rn(R[6], rz));
    float dy = __fadd_rn(__fadd_rn(__fmul_rn(R[1], rx), __fmul_rn(R[4], ry)),
                         __fmul_rn(R[7], rz));
    float dz = __fadd_rn(__fadd_rn(__fmul_rn(R[2], rx), __fmul_rn(R[5], ry)),
                         __fmul_rn(R[8], rz));
    float n2 = __fadd_rn(__fadd_rn(__fmul_rn(dx, dx), __fmul_rn(dy, dy)),
                         __fmul_rn(dz, dz));
    float nrm = sqrtf(n2);
    dx = __fdiv_rn(dx, nrm);
    dy = __fdiv_rn(dy, nrm);
    dz = __fdiv_rn(dz, nrm);

    float cx = campos[b * 3 + 0];
    float cy = campos[b * 3 + 1];
    float cz = campos[b * 3 + 2];

    // --- AABB [-1,1]^3 intersection (IEEE divisions; inf semantics ok) ---
    float t1x = __fdiv_rn(__fsub_rn(-1.0f, cx), dx);
    float t2x = __fdiv_rn(__fsub_rn( 1.0f, cx), dx);
    float t1y = __fdiv_rn(__fsub_rn(-1.0f, cy), dy);
    float t2y = __fdiv_rn(__fsub_rn( 1.0f, cy), dy);
    float t1z = __fdiv_rn(__fsub_rn(-1.0f, cz), dz);
    float t2z = __fdiv_rn(__fsub_rn( 1.0f, cz), dz);
    float tmin = fmaxf(fminf(t1x, t2x), fmaxf(fminf(t1y, t2y), fminf(t1z, t2z)));
    float tmax = fminf(fmaxf(t1x, t2x), fminf(fmaxf(t1y, t2y), fmaxf(t1z, t2z)));
    bool hit = tmin < tmax;
    float t0 = fmaxf(hit ? tmin : 0.0f, 0.0f);

    // raypos = campos + raydir * t0 (unfused, matches reference rounding)
    float pAx = __fadd_rn(cx, __fmul_rn(dx, t0));
    float pAy = __fadd_rn(cy, __fmul_rn(dy, t0));
    float pAz = __fadd_rn(cz, __fmul_rn(dz, t0));

    // per-step increment raydir*DT (reference recomputes; same rounded value)
    float sx = __fmul_rn(dx, DT);
    float sy = __fmul_rn(dy, DT);
    float sz = __fmul_rn(dz, DT);

    float r_out = 0.0f, g_out = 0.0f, b_out = 0.0f, a_out = 0.0f;

    if (hit) {
        const float4* __restrict__ vb = g_vol + (long)b * D3;
        // steps beyond kmax are guaranteed geometrically invalid
        // (t - t0 > tmax - t0 + 2*DT  >>  fp drift); cap at reference count.
        int kmax = (int)((tmax - t0) * 32.0f) + 3;
        if (kmax > NSTEPS) kmax = NSTEPS;

        #pragma unroll 1
        for (int k = 0; k < kmax; k += 2) {
            // substep B position (exact add chain, same as reference)
            float pBx = __fadd_rn(pAx, sx);
            float pBy = __fadd_rn(pAy, sy);
            float pBz = __fadd_rn(pAz, sz);

            bool vA = (pAx > -1.0f) & (pAx < 1.0f) &
                      (pAy > -1.0f) & (pAy < 1.0f) &
                      (pAz > -1.0f) & (pAz < 1.0f);
            bool vB = (pBx > -1.0f) & (pBx < 1.0f) &
                      (pBy > -1.0f) & (pBy < 1.0f) &
                      (pBz > -1.0f) & (pBz < 1.0f);

            // grid coords + clamped indices (safe for invalid lanes too)
            float gAx = fmaf(pAx, 63.5f, 63.5f);
            float gAy = fmaf(pAy, 63.5f, 63.5f);
            float gAz = fmaf(pAz, 63.5f, 63.5f);
            float gBx = fmaf(pBx, 63.5f, 63.5f);
            float gBy = fmaf(pBy, 63.5f, 63.5f);
            float gBz = fmaf(pBz, 63.5f, 63.5f);
            int ax0 = min(max(__float2int_rd(gAx), 0), DD - 2);
            int ay0 = min(max(__float2int_rd(gAy), 0), DD - 2);
            int az0 = min(max(__float2int_rd(gAz), 0), DD - 2);
            int bx0 = min(max(__float2int_rd(gBx), 0), DD - 2);
            int by0 = min(max(__float2int_rd(gBy), 0), DD - 2);
            int bz0 = min(max(__float2int_rd(gBz), 0), DD - 2);

            const float4* pa = vb + ((az0 << 14) + (ay0 << 7) + ax0);
            const float4* pb = vb + ((bz0 << 14) + (by0 << 7) + bx0);

            // 16 loads in flight
            float4 A000 = __ldg(pa);
            float4 A001 = __ldg(pa + 1);
            float4 A010 = __ldg(pa + DD);
            float4 A011 = __ldg(pa + DD + 1);
            float4 A100 = __ldg(pa + DD * DD);
            float4 A101 = __ldg(pa + DD * DD + 1);
            float4 A110 = __ldg(pa + DD * DD + DD);
            float4 A111 = __ldg(pa + DD * DD + DD + 1);
            float4 B000 = __ldg(pb);
            float4 B001 = __ldg(pb + 1);
            float4 B010 = __ldg(pb + DD);
            float4 B011 = __ldg(pb + DD + 1);
            float4 B100 = __ldg(pb + DD * DD);
            float4 B101 = __ldg(pb + DD * DD + 1);
            float4 B110 = __ldg(pb + DD * DD + DD);
            float4 B111 = __ldg(pb + DD * DD + DD + 1);

            // load-independent weight math overlaps load latency
            float afx = gAx - (float)ax0, afy = gAy - (float)ay0, afz = gAz - (float)az0;
            float bfx = gBx - (float)bx0, bfy = gBy - (float)by0, bfz = gBz - (float)bz0;
            float aw00 = (1.0f - afz) * (1.0f - afy), aw01 = (1.0f - afz) * afy;
            float aw10 = afz * (1.0f - afy),          aw11 = afz * afy;
            float awx0 = 1.0f - afx;
            float aw000 = aw00 * awx0, aw001 = aw00 * afx;
            float aw010 = aw01 * awx0, aw011 = aw01 * afx;
            float aw100 = aw10 * awx0, aw101 = aw10 * afx;
            float aw110 = aw11 * awx0, aw111 = aw11 * afx;
            float bw00 = (1.0f - bfz) * (1.0f - bfy), bw01 = (1.0f - bfz) * bfy;
            float bw10 = bfz * (1.0f - bfy),          bw11 = bfz * bfy;
            float bwx0 = 1.0f - bfx;
            float bw000 = bw00 * bwx0, bw001 = bw00 * bfx;
            float bw010 = bw01 * bwx0, bw011 = bw01 * bfx;
            float bw100 = bw10 * bwx0, bw101 = bw10 * bfx;
            float bw110 = bw11 * bwx0, bw111 = bw11 * bfx;

            if (vA) {
                float s0, s1, s2, s3;
                s0 = aw000 * A000.x; s1 = aw000 * A000.y;
                s2 = aw000 * A000.z; s3 = aw000 * A000.w;
                s0 = fmaf(aw001, A001.x, s0); s1 = fmaf(aw001, A001.y, s1);
                s2 = fmaf(aw001, A001.z, s2); s3 = fmaf(aw001, A001.w, s3);
                s0 = fmaf(aw010, A010.x, s0); s1 = fmaf(aw010, A010.y, s1);
                s2 = fmaf(aw010, A010.z, s2); s3 = fmaf(aw010, A010.w, s3);
                s0 = fmaf(aw011, A011.x, s0); s1 = fmaf(aw011, A011.y, s1);
                s2 = fmaf(aw011, A011.z, s2); s3 = fmaf(aw011, A011.w, s3);
                s0 = fmaf(aw100, A100.x, s0); s1 = fmaf(aw100, A100.y, s1);
                s2 = fmaf(aw100, A100.z, s2); s3 = fmaf(aw100, A100.w, s3);
                s0 = fmaf(aw101, A101.x, s0); s1 = fmaf(aw101, A101.y, s1);
                s2 = fmaf(aw101, A101.z, s2); s3 = fmaf(aw101, A101.w, s3);
                s0 = fmaf(aw110, A110.x, s0); s1 = fmaf(aw110, A110.y, s1);
                s2 = fmaf(aw110, A110.z, s2); s3 = fmaf(aw110, A110.w, s3);
                s0 = fmaf(aw111, A111.x, s0); s1 = fmaf(aw111, A111.y, s1);
                s2 = fmaf(aw111, A111.z, s2); s3 = fmaf(aw111, A111.w, s3);
                float contrib = __fsub_rn(
                    fminf(__fadd_rn(a_out, __fmul_rn(s3, DT)), 1.0f), a_out);
                r_out = __fadd_rn(r_out, __fmul_rn(s0, contrib));
                g_out = __fadd_rn(g_out, __fmul_rn(s1, contrib));
                b_out = __fadd_rn(b_out, __fmul_rn(s2, contrib));
                a_out = __fadd_rn(a_out, contrib);
            }
            if (vB) {
                float s0, s1, s2, s3;
                s0 = bw000 * B000.x; s1 = bw000 * B000.y;
                s2 = bw000 * B000.z; s3 = bw000 * B000.w;
                s0 = fmaf(bw001, B001.x, s0); s1 = fmaf(bw001, B001.y, s1);
                s2 = fmaf(bw001, B001.z, s2); s3 = fmaf(bw001, B001.w, s3);
                s0 = fmaf(bw010, B010.x, s0); s1 = fmaf(bw010, B010.y, s1);
                s2 = fmaf(bw010, B010.z, s2); s3 = fmaf(bw010, B010.w, s3);
                s0 = fmaf(bw011, B011.x, s0); s1 = fmaf(bw011, B011.y, s1);
                s2 = fmaf(bw011, B011.z, s2); s3 = fmaf(bw011, B011.w, s3);
                s0 = fmaf(bw100, B100.x, s0); s1 = fmaf(bw100, B100.y, s1);
                s2 = fmaf(bw100, B100.z, s2); s3 = fmaf(bw100, B100.w, s3);
                s0 = fmaf(bw101, B101.x, s0); s1 = fmaf(bw101, B101.y, s1);
                s2 = fmaf(bw101, B101.z, s2); s3 = fmaf(bw101, B101.w, s3);
                s0 = fmaf(bw110, B110.x, s0); s1 = fmaf(bw110, B110.y, s1);
                s2 = fmaf(bw110, B110.z, s2); s3 = fmaf(bw110, B110.w, s3);
                s0 = fmaf(bw111, B111.x, s0); s1 = fmaf(bw111, B111.y, s1);
                s2 = fmaf(bw111, B111.z, s2); s3 = fmaf(bw111, B111.w, s3);
                float contrib = __fsub_rn(
                    fminf(__fadd_rn(a_out, __fmul_rn(s3, DT)), 1.0f), a_out);
                r_out = __fadd_rn(r_out, __fmul_rn(s0, contrib));
                g_out = __fadd_rn(g_out, __fmul_rn(s1, contrib));
                b_out = __fadd_rn(b_out, __fmul_rn(s2, contrib));
                a_out = __fadd_rn(a_out, contrib);
            }
            // advance two steps (exact chain)
            pAx = __fadd_rn(pBx, sx);
            pAy = __fadd_rn(pBy, sy);
            pAz = __fadd_rn(pBz, sz);
            // once alpha saturates it is exactly 1.0 -> all later contribs 0
            if (a_out >= 1.0f) break;
        }
    }

    long obase = (((long)b * 4) * HH + y) * WW + x;
    const long cstride = (long)HH * WW;
    out[obase + 0 * cstride] = r_out;
    out[obase + 1 * cstride] = g_out;
    out[obase + 2 * cstride] = b_out;
    out[obase + 3 * cstride] = a_out;
}

extern "C" void kernel_launch(void* const* d_in, const int* in_sizes, int n_in,
                              void* d_out, int out_size) {
    const float* camrot      = (const float*)d_in[0];
    const float* campos      = (const float*)d_in[1];
    const float* focal       = (const float*)d_in[2];
    const float* princpt     = (const float*)d_in[3];
    const float* pixelcoords = (const float*)d_in[4];
    const float* volume      = (const float*)d_in[5];
    float* out = (float*)d_out;

    {
        long n4 = (long)BB * (D3 / 4);
        int threads = 256;
        int blocks = (int)((n4 + threads - 1) / threads);
        interleave_kernel<<<blocks, threads>>>((const float4*)volume);
    }
    {
        dim3 block(16, 8, 1);
        dim3 grid(WW / 16, HH / 8, BB);
        raymarch_kernel<<<grid, block>>>(camrot, campos, focal, princpt,
                                         pixelcoords, out);
    }
}

// round 5
// speedup vs baseline: 1.0527x; 1.0527x over previous
#include <cuda_runtime.h>
#include <cuda_fp16.h>
#include <math.h>

// Problem constants (from reference setup_inputs)
#define BB 2
#define HH 256
#define WW 256
#define DD 128
#define D3 (DD * DD * DD)
#define DT 0.03125f
#define NSTEPS 111

// Dual-parity half4-interleaved volume copies. Each uint4 entry = 2 voxels
// x 4 channels in fp16: (r0,g0),(b0,a0),(r1,g1),(b1,a1).
//  g_volA entry i = voxels (2i, 2i+1)   -> even x0 pairs
//  g_volB entry i = voxels (2i+1, 2i+2) -> odd  x0 pairs (entry 63 of each
//                   row is padding, never read since x0 <= 126)
__device__ uint4 g_volA[BB * D3 / 2];
__device__ uint4 g_volB[BB * D3 / 2];

__device__ __forceinline__ unsigned pack2h(float lo, float hi) {
    __half2 h = __floats2half2_rn(lo, hi);
    return *reinterpret_cast<unsigned*>(&h);
}

__device__ __forceinline__ uint4 pack8h(float r0, float g0, float b0, float a0,
                                        float r1, float g1, float b1, float a1) {
    uint4 u;
    u.x = pack2h(r0, g0);
    u.y = pack2h(b0, a0);
    u.z = pack2h(r1, g1);
    u.w = pack2h(b1, a1);
    return u;
}

// ---------------------------------------------------------------------------
// Pass 1: interleave + fp16-pack. Each thread handles 4 voxels (one float4
// per channel) and emits 2 entries into each parity copy.
// ---------------------------------------------------------------------------
__global__ void interleave_kernel(const float4* __restrict__ vol4,
                                  const float* __restrict__ vol) {
    const int QP = D3 / 4;
    long i = (long)blockIdx.x * blockDim.x + threadIdx.x;
    if (i >= (long)BB * QP) return;
    int b = (int)(i / QP);
    int s4 = (int)(i % QP);
    const float4* base4 = vol4 + (long)b * 4 * QP;
    float4 c0 = __ldg(base4 + 0 * QP + s4);
    float4 c1 = __ldg(base4 + 1 * QP + s4);
    float4 c2 = __ldg(base4 + 2 * QP + s4);
    float4 c3 = __ldg(base4 + 3 * QP + s4);
    // next voxel (for B's straddling pair); clamp to stay in-bounds
    int vn = min(s4 * 4 + 4, D3 - 1);
    const float* basef = vol + (long)b * 4 * D3;
    float n0 = __ldg(basef + 0 * D3 + vn);
    float n1 = __ldg(basef + 1 * D3 + vn);
    float n2 = __ldg(basef + 2 * D3 + vn);
    float n3 = __ldg(basef + 3 * D3 + vn);

    long o = (long)b * (D3 / 2) + (long)s4 * 2;
    g_volA[o + 0] = pack8h(c0.x, c1.x, c2.x, c3.x, c0.y, c1.y, c2.y, c3.y);
    g_volA[o + 1] = pack8h(c0.z, c1.z, c2.z, c3.z, c0.w, c1.w, c2.w, c3.w);
    g_volB[o + 0] = pack8h(c0.y, c1.y, c2.y, c3.y, c0.z, c1.z, c2.z, c3.z);
    g_volB[o + 1] = pack8h(c0.w, c1.w, c2.w, c3.w, n0, n1, n2, n3);
}

// Accumulate a corner pair (weights w0 for left voxel, w1 for right)
__device__ __forceinline__ void acc_pair(uint4 U, float w0, float w1,
                                         float& s0, float& s1,
                                         float& s2, float& s3) {
    float2 rg0 = __half22float2(*reinterpret_cast<const __half2*>(&U.x));
    float2 ba0 = __half22float2(*reinterpret_cast<const __half2*>(&U.y));
    float2 rg1 = __half22float2(*reinterpret_cast<const __half2*>(&U.z));
    float2 ba1 = __half22float2(*reinterpret_cast<const __half2*>(&U.w));
    s0 = fmaf(w0, rg0.x, s0); s1 = fmaf(w0, rg0.y, s1);
    s2 = fmaf(w0, ba0.x, s2); s3 = fmaf(w0, ba0.y, s3);
    s0 = fmaf(w1, rg1.x, s0); s1 = fmaf(w1, rg1.y, s1);
    s2 = fmaf(w1, ba1.x, s2); s3 = fmaf(w1, ba1.y, s3);
}

// ---------------------------------------------------------------------------
// Pass 2: ray march. One thread per pixel, warp covers an 8x4 pixel tile.
// Ray setup + position stepping replicate the reference's IEEE fp32 ops
// bit-exactly (unfused _rn intrinsics): step-0 validity is a knife-edge
// (entry position lies exactly on the cube face). Everything downstream of a
// valid position is smooth; fp16 volume quantization is a ~2^-11 relative
// perturbation on samples, well under the 1e-3 budget.
// ---------------------------------------------------------------------------
__global__ void __launch_bounds__(128, 8)
raymarch_kernel(const float* __restrict__ camrot,
                const float* __restrict__ campos,
                const float* __restrict__ focal,
                const float* __restrict__ princpt,
                const float* __restrict__ pixelcoords,
                float* __restrict__ out) {
    int x = blockIdx.x * blockDim.x + threadIdx.x;
    int y = blockIdx.y * blockDim.y + threadIdx.y;
    int b = blockIdx.z;

    // --- camera ray (bit-exact vs reference) ---
    long pidx = (((long)b * HH + y) * WW + x) * 2;
    float px = pixelcoords[pidx + 0];
    float py = pixelcoords[pidx + 1];
    float rx = __fdiv_rn(__fsub_rn(px, princpt[b * 2 + 0]), focal[b * 2 + 0]);
    float ry = __fdiv_rn(__fsub_rn(py, princpt[b * 2 + 1]), focal[b * 2 + 1]);
    float rz = 1.0f;
    const float* R = camrot + b * 9;  // dir_j = sum_i R[i][j] * r_i
    float dx = __fadd_rn(__fadd_rn(__fmul_rn(R[0], rx), __fmul_rn(R[3], ry)),
                         __fmul_rn(R[6], rz));
    float dy = __fadd_rn(__fadd_rn(__fmul_rn(R[1], rx), __fmul_rn(R[4], ry)),
                         __fmul_rn(R[7], rz));
    float dz = __fadd_rn(__fadd_rn(__fmul_rn(R[2], rx), __fmul_rn(R[5], ry)),
                         __fmul_rn(R[8], rz));
    float n2 = __fadd_rn(__fadd_rn(__fmul_rn(dx, dx), __fmul_rn(dy, dy)),
                         __fmul_rn(dz, dz));
    float nrm = sqrtf(n2);
    dx = __fdiv_rn(dx, nrm);
    dy = __fdiv_rn(dy, nrm);
    dz = __fdiv_rn(dz, nrm);

    float cx = campos[b * 3 + 0];
    float cy = campos[b * 3 + 1];
    float cz = campos[b * 3 + 2];

    // --- AABB [-1,1]^3 intersection (IEEE divisions; inf semantics ok) ---
    float t1x = __fdiv_rn(__fsub_rn(-1.0f, cx), dx);
    float t2x = __fdiv_rn(__fsub_rn( 1.0f, cx), dx);
    float t1y = __fdiv_rn(__fsub_rn(-1.0f, cy), dy);
    float t2y = __fdiv_rn(__fsub_rn( 1.0f, cy), dy);
    float t1z = __fdiv_rn(__fsub_rn(-1.0f, cz), dz);
    float t2z = __fdiv_rn(__fsub_rn( 1.0f, cz), dz);
    float tmin = fmaxf(fminf(t1x, t2x), fmaxf(fminf(t1y, t2y), fminf(t1z, t2z)));
    float tmax = fminf(fmaxf(t1x, t2x), fminf(fmaxf(t1y, t2y), fmaxf(t1z, t2z)));
    bool hit = tmin < tmax;
    float t0 = fmaxf(hit ? tmin : 0.0f, 0.0f);

    // raypos = campos + raydir * t0 (unfused, matches reference rounding)
    float posx = __fadd_rn(cx, __fmul_rn(dx, t0));
    float posy = __fadd_rn(cy, __fmul_rn(dy, t0));
    float posz = __fadd_rn(cz, __fmul_rn(dz, t0));

    // per-step increment raydir*DT (reference recomputes; same rounded value)
    float sx = __fmul_rn(dx, DT);
    float sy = __fmul_rn(dy, DT);
    float sz = __fmul_rn(dz, DT);

    float r_out = 0.0f, g_out = 0.0f, b_out = 0.0f, a_out = 0.0f;

    if (hit) {
        const uint4* __restrict__ vbA = g_volA + (long)b * (D3 / 2);
        const uint4* __restrict__ vbB = g_volB + (long)b * (D3 / 2);
        // steps beyond kmax are geometrically invalid (validated in R4)
        int kmax = (int)((tmax - t0) * 32.0f) + 3;
        if (kmax > NSTEPS) kmax = NSTEPS;

        #pragma unroll 1
        for (int k = 0; k < kmax; k++) {
            bool valid = (posx > -1.0f) & (posx < 1.0f) &
                         (posy > -1.0f) & (posy < 1.0f) &
                         (posz > -1.0f) & (posz < 1.0f);
            if (valid) {
                // grid coords (smooth path; pos strictly inside (-1,1))
                float gx = fmaf(posx, 63.5f, 63.5f);
                float gy = fmaf(posy, 63.5f, 63.5f);
                float gz = fmaf(posz, 63.5f, 63.5f);
                int x0 = min((int)gx, DD - 2);
                int y0 = min((int)gy, DD - 2);
                int z0 = min((int)gz, DD - 2);

                // parity-selected copy: one LDG.128 covers a corner pair
                const uint4* __restrict__ volp = (x0 & 1) ? vbB : vbA;
                int base = (((z0 << 7) + y0) << 6) + (x0 >> 1);
                uint4 U00 = __ldg(volp + base);
                uint4 U01 = __ldg(volp + base + 64);              // y+1
                uint4 U10 = __ldg(volp + base + 64 * 128);        // z+1
                uint4 U11 = __ldg(volp + base + 64 * 128 + 64);   // z+1,y+1

                // load-independent weight math overlaps load latency
                float fx = gx - (float)x0;
                float fy = gy - (float)y0;
                float fz = gz - (float)z0;
                float wx0 = 1.0f - fx;
                float w00 = (1.0f - fz) * (1.0f - fy);
                float w01 = (1.0f - fz) * fy;
                float w10 = fz * (1.0f - fy);
                float w11 = fz * fy;

                float s0 = 0.0f, s1 = 0.0f, s2 = 0.0f, s3 = 0.0f;
                acc_pair(U00, w00 * wx0, w00 * fx, s0, s1, s2, s3);
                acc_pair(U01, w01 * wx0, w01 * fx, s0, s1, s2, s3);
                acc_pair(U10, w10 * wx0, w10 * fx, s0, s1, s2, s3);
                acc_pair(U11, w11 * wx0, w11 * fx, s0, s1, s2, s3);

                float contrib = __fsub_rn(
                    fminf(__fadd_rn(a_out, __fmul_rn(s3, DT)), 1.0f), a_out);
                r_out = __fadd_rn(r_out, __fmul_rn(s0, contrib));
                g_out = __fadd_rn(g_out, __fmul_rn(s1, contrib));
                b_out = __fadd_rn(b_out, __fmul_rn(s2, contrib));
                a_out = __fadd_rn(a_out, contrib);
                if (a_out >= 1.0f) break;  // exactly 1 -> future contribs 0
            }
            // exact position advance (knife-edge-sensitive)
            posx = __fadd_rn(posx, sx);
            posy = __fadd_rn(posy, sy);
            posz = __fadd_rn(posz, sz);
        }
    }

    long obase = (((long)b * 4) * HH + y) * WW + x;
    const long cstride = (long)HH * WW;
    out[obase + 0 * cstride] = r_out;
    out[obase + 1 * cstride] = g_out;
    out[obase + 2 * cstride] = b_out;
    out[obase + 3 * cstride] = a_out;
}

extern "C" void kernel_launch(void* const* d_in, const int* in_sizes, int n_in,
                              void* d_out, int out_size) {
    const float* camrot      = (const float*)d_in[0];
    const float* campos      = (const float*)d_in[1];
    const float* focal       = (const float*)d_in[2];
    const float* princpt     = (const float*)d_in[3];
    const float* pixelcoords = (const float*)d_in[4];
    const float* volume      = (const float*)d_in[5];
    float* out = (float*)d_out;

    {
        long n = (long)BB * (D3 / 4);
        int threads = 256;
        int blocks = (int)((n + threads - 1) / threads);
        interleave_kernel<<<blocks, threads>>>((const float4*)volume, volume);
    }
    {
        dim3 block(8, 16, 1);   // warp = 8x4 pixel tile (tight ray bundles)
        dim3 grid(WW / 8, HH / 16, BB);
        raymarch_kernel<<<grid, block>>>(camrot, campos, focal, princpt,
                                         pixelcoords, out);
    }
}

// round 6
// speedup vs baseline: 1.1108x; 1.0552x over previous
#include <cuda_runtime.h>
#include <cuda_fp16.h>
#include <math.h>

// Problem constants (from reference setup_inputs)
#define BB 2
#define HH 256
#define WW 256
#define DD 128
#define D3 (DD * DD * DD)
#define DT 0.03125f
#define NSTEPS 111

// Dual-parity half4-interleaved volume copies. Each uint4 entry = 2 voxels
// x 4 channels in fp16: (r0,g0),(b0,a0),(r1,g1),(b1,a1).
//  g_volA entry i = voxels (2i, 2i+1)   -> even x0 pairs
//  g_volB entry i = voxels (2i+1, 2i+2) -> odd  x0 pairs (entry 63 of each
//                   row is padding, never read since x0 <= 126)
__device__ uint4 g_volA[BB * D3 / 2];
__device__ uint4 g_volB[BB * D3 / 2];

__device__ __forceinline__ unsigned pack2h(float lo, float hi) {
    __half2 h = __floats2half2_rn(lo, hi);
    return *reinterpret_cast<unsigned*>(&h);
}

__device__ __forceinline__ uint4 pack8h(float r0, float g0, float b0, float a0,
                                        float r1, float g1, float b1, float a1) {
    uint4 u;
    u.x = pack2h(r0, g0);
    u.y = pack2h(b0, a0);
    u.z = pack2h(r1, g1);
    u.w = pack2h(b1, a1);
    return u;
}

// ---------------------------------------------------------------------------
// Pass 1: interleave + fp16-pack. Each thread handles 4 voxels; the
// straddling "next voxel" for copy B comes from lane+1 via shuffle
// (gmem fallback only on warp/array boundary).
// ---------------------------------------------------------------------------
__global__ void interleave_kernel(const float4* __restrict__ vol4,
                                  const float* __restrict__ vol) {
    const int QP = D3 / 4;
    long i = (long)blockIdx.x * blockDim.x + threadIdx.x;
    if (i >= (long)BB * QP) return;
    int b = (int)(i / QP);
    int s4 = (int)(i % QP);
    const float4* base4 = vol4 + (long)b * 4 * QP;
    float4 c0 = __ldg(base4 + 0 * QP + s4);
    float4 c1 = __ldg(base4 + 1 * QP + s4);
    float4 c2 = __ldg(base4 + 2 * QP + s4);
    float4 c3 = __ldg(base4 + 3 * QP + s4);

    // next voxel (4*s4+4) channel values: lane+1's (c0.x,c1.x,c2.x,c3.x)
    int lane = threadIdx.x & 31;
    float n0 = __shfl_down_sync(0xffffffffu, c0.x, 1);
    float n1 = __shfl_down_sync(0xffffffffu, c1.x, 1);
    float n2 = __shfl_down_sync(0xffffffffu, c2.x, 1);
    float n3 = __shfl_down_sync(0xffffffffu, c3.x, 1);
    if (lane == 31 || s4 == QP - 1) {  // warp or array boundary: gmem
        int vn = min(s4 * 4 + 4, D3 - 1);
        const float* basef = vol + (long)b * 4 * D3;
        n0 = __ldg(basef + 0 * D3 + vn);
        n1 = __ldg(basef + 1 * D3 + vn);
        n2 = __ldg(basef + 2 * D3 + vn);
        n3 = __ldg(basef + 3 * D3 + vn);
    }

    long o = (long)b * (D3 / 2) + (long)s4 * 2;
    g_volA[o + 0] = pack8h(c0.x, c1.x, c2.x, c3.x, c0.y, c1.y, c2.y, c3.y);
    g_volA[o + 1] = pack8h(c0.z, c1.z, c2.z, c3.z, c0.w, c1.w, c2.w, c3.w);
    g_volB[o + 0] = pack8h(c0.y, c1.y, c2.y, c3.y, c0.z, c1.z, c2.z, c3.z);
    g_volB[o + 1] = pack8h(c0.w, c1.w, c2.w, c3.w, n0, n1, n2, n3);
}

// Accumulate a corner pair (weights w0 for left voxel, w1 for right)
__device__ __forceinline__ void acc_pair(uint4 U, float w0, float w1,
                                         float& s0, float& s1,
                                         float& s2, float& s3) {
    float2 rg0 = __half22float2(*reinterpret_cast<const __half2*>(&U.x));
    float2 ba0 = __half22float2(*reinterpret_cast<const __half2*>(&U.y));
    float2 rg1 = __half22float2(*reinterpret_cast<const __half2*>(&U.z));
    float2 ba1 = __half22float2(*reinterpret_cast<const __half2*>(&U.w));
    s0 = fmaf(w0, rg0.x, s0); s1 = fmaf(w0, rg0.y, s1);
    s2 = fmaf(w0, ba0.x, s2); s3 = fmaf(w0, ba0.y, s3);
    s0 = fmaf(w1, rg1.x, s0); s1 = fmaf(w1, rg1.y, s1);
    s2 = fmaf(w1, ba1.x, s2); s3 = fmaf(w1, ba1.y, s3);
}

// Prepare one march step at position p: validity, interpolation fractions,
// and the 4 in-flight corner-pair loads (parity-selected copy).
// Safe for out-of-range p (indices clamped; caller gates on valid).
__device__ __forceinline__ void prep_step(
    const uint4* __restrict__ vbA, const uint4* __restrict__ vbB,
    float pxp, float pyp, float pzp,
    bool& valid, float& fx, float& fy, float& fz,
    uint4& U00, uint4& U01, uint4& U10, uint4& U11) {
    valid = (pxp > -1.0f) & (pxp < 1.0f) &
            (pyp > -1.0f) & (pyp < 1.0f) &
            (pzp > -1.0f) & (pzp < 1.0f);
    float gx = fmaf(pxp, 63.5f, 63.5f);
    float gy = fmaf(pyp, 63.5f, 63.5f);
    float gz = fmaf(pzp, 63.5f, 63.5f);
    int x0 = min(max(__float2int_rd(gx), 0), DD - 2);
    int y0 = min(max(__float2int_rd(gy), 0), DD - 2);
    int z0 = min(max(__float2int_rd(gz), 0), DD - 2);
    fx = gx - (float)x0;
    fy = gy - (float)y0;
    fz = gz - (float)z0;
    const uint4* __restrict__ volp = (x0 & 1) ? vbB : vbA;
    int base = (((z0 << 7) + y0) << 6) + (x0 >> 1);
    U00 = __ldg(volp + base);
    U01 = __ldg(volp + base + 64);              // y+1
    U10 = __ldg(volp + base + 64 * 128);        // z+1
    U11 = __ldg(volp + base + 64 * 128 + 64);   // z+1,y+1
}

// ---------------------------------------------------------------------------
// Pass 2: ray march with depth-1 load prefetch. One thread per pixel, warp
// covers an 8x4 pixel tile. Ray setup + position stepping replicate the
// reference's IEEE fp32 ops bit-exactly (unfused _rn intrinsics): step-0
// validity is a knife-edge (entry position lies exactly on the cube face).
// Everything downstream of a valid position is smooth.
// ---------------------------------------------------------------------------
__global__ void __launch_bounds__(128, 7)
raymarch_kernel(const float* __restrict__ camrot,
                const float* __restrict__ campos,
                const float* __restrict__ focal,
                const float* __restrict__ princpt,
                const float* __restrict__ pixelcoords,
                float* __restrict__ out) {
    int x = blockIdx.x * blockDim.x + threadIdx.x;
    int y = blockIdx.y * blockDim.y + threadIdx.y;
    int b = blockIdx.z;

    // --- camera ray (bit-exact vs reference) ---
    long pidx = (((long)b * HH + y) * WW + x) * 2;
    float px = pixelcoords[pidx + 0];
    float py = pixelcoords[pidx + 1];
    float rx = __fdiv_rn(__fsub_rn(px, princpt[b * 2 + 0]), focal[b * 2 + 0]);
    float ry = __fdiv_rn(__fsub_rn(py, princpt[b * 2 + 1]), focal[b * 2 + 1]);
    float rz = 1.0f;
    const float* R = camrot + b * 9;  // dir_j = sum_i R[i][j] * r_i
    float dx = __fadd_rn(__fadd_rn(__fmul_rn(R[0], rx), __fmul_rn(R[3], ry)),
                         __fmul_rn(R[6], rz));
    float dy = __fadd_rn(__fadd_rn(__fmul_rn(R[1], rx), __fmul_rn(R[4], ry)),
                         __fmul_rn(R[7], rz));
    float dz = __fadd_rn(__fadd_rn(__fmul_rn(R[2], rx), __fmul_rn(R[5], ry)),
                         __fmul_rn(R[8], rz));
    float n2 = __fadd_rn(__fadd_rn(__fmul_rn(dx, dx), __fmul_rn(dy, dy)),
                         __fmul_rn(dz, dz));
    float nrm = sqrtf(n2);
    dx = __fdiv_rn(dx, nrm);
    dy = __fdiv_rn(dy, nrm);
    dz = __fdiv_rn(dz, nrm);

    float cx = campos[b * 3 + 0];
    float cy = campos[b * 3 + 1];
    float cz = campos[b * 3 + 2];

    // --- AABB [-1,1]^3 intersection (IEEE divisions; inf semantics ok) ---
    float t1x = __fdiv_rn(__fsub_rn(-1.0f, cx), dx);
    float t2x = __fdiv_rn(__fsub_rn( 1.0f, cx), dx);
    float t1y = __fdiv_rn(__fsub_rn(-1.0f, cy), dy);
    float t2y = __fdiv_rn(__fsub_rn( 1.0f, cy), dy);
    float t1z = __fdiv_rn(__fsub_rn(-1.0f, cz), dz);
    float t2z = __fdiv_rn(__fsub_rn( 1.0f, cz), dz);
    float tmin = fmaxf(fminf(t1x, t2x), fmaxf(fminf(t1y, t2y), fminf(t1z, t2z)));
    float tmax = fminf(fmaxf(t1x, t2x), fminf(fmaxf(t1y, t2y), fmaxf(t1z, t2z)));
    bool hit = tmin < tmax;
    float t0 = fmaxf(hit ? tmin : 0.0f, 0.0f);

    // raypos = campos + raydir * t0 (unfused, matches reference rounding)
    float posx = __fadd_rn(cx, __fmul_rn(dx, t0));
    float posy = __fadd_rn(cy, __fmul_rn(dy, t0));
    float posz = __fadd_rn(cz, __fmul_rn(dz, t0));

    // per-step increment raydir*DT (reference recomputes; same rounded value)
    float sx = __fmul_rn(dx, DT);
    float sy = __fmul_rn(dy, DT);
    float sz = __fmul_rn(dz, DT);

    float r_out = 0.0f, g_out = 0.0f, b_out = 0.0f, a_out = 0.0f;

    if (hit) {
        const uint4* __restrict__ vbA = g_volA + (long)b * (D3 / 2);
        const uint4* __restrict__ vbB = g_volB + (long)b * (D3 / 2);
        // steps beyond kmax are geometrically invalid (validated in R4/R5)
        int kmax = (int)((tmax - t0) * 32.0f) + 3;
        if (kmax > NSTEPS) kmax = NSTEPS;

        // prologue: prefetch step 0
        bool valid; float fx, fy, fz;
        uint4 U00, U01, U10, U11;
        prep_step(vbA, vbB, posx, posy, posz,
                  valid, fx, fy, fz, U00, U01, U10, U11);

        #pragma unroll 1
        for (int k = 0; k < kmax; k++) {
            // advance position (exact chain, knife-edge-sensitive)
            float npx = __fadd_rn(posx, sx);
            float npy = __fadd_rn(posy, sy);
            float npz = __fadd_rn(posz, sz);

            // prefetch next step's loads before consuming current
            bool nvalid; float nfx, nfy, nfz;
            uint4 N00, N01, N10, N11;
            prep_step(vbA, vbB, npx, npy, npz,
                      nvalid, nfx, nfy, nfz, N00, N01, N10, N11);

            if (valid) {
                float wx0 = 1.0f - fx;
                float w00 = (1.0f - fz) * (1.0f - fy);
                float w01 = (1.0f - fz) * fy;
                float w10 = fz * (1.0f - fy);
                float w11 = fz * fy;

                float s0 = 0.0f, s1 = 0.0f, s2 = 0.0f, s3 = 0.0f;
                acc_pair(U00, w00 * wx0, w00 * fx, s0, s1, s2, s3);
                acc_pair(U01, w01 * wx0, w01 * fx, s0, s1, s2, s3);
                acc_pair(U10, w10 * wx0, w10 * fx, s0, s1, s2, s3);
                acc_pair(U11, w11 * wx0, w11 * fx, s0, s1, s2, s3);

                float contrib = __fsub_rn(
                    fminf(__fadd_rn(a_out, __fmul_rn(s3, DT)), 1.0f), a_out);
                r_out = __fadd_rn(r_out, __fmul_rn(s0, contrib));
                g_out = __fadd_rn(g_out, __fmul_rn(s1, contrib));
                b_out = __fadd_rn(b_out, __fmul_rn(s2, contrib));
                a_out = __fadd_rn(a_out, contrib);
                if (a_out >= 1.0f) break;  // exactly 1 -> future contribs 0
            }
            // rotate pipeline
            posx = npx; posy = npy; posz = npz;
            valid = nvalid; fx = nfx; fy = nfy; fz = nfz;
            U00 = N00; U01 = N01; U10 = N10; U11 = N11;
        }
    }

    long obase = (((long)b * 4) * HH + y) * WW + x;
    const long cstride = (long)HH * WW;
    out[obase + 0 * cstride] = r_out;
    out[obase + 1 * cstride] = g_out;
    out[obase + 2 * cstride] = b_out;
    out[obase + 3 * cstride] = a_out;
}

extern "C" void kernel_launch(void* const* d_in, const int* in_sizes, int n_in,
                              void* d_out, int out_size) {
    const float* camrot      = (const float*)d_in[0];
    const float* campos      = (const float*)d_in[1];
    const float* focal       = (const float*)d_in[2];
    const float* princpt     = (const float*)d_in[3];
    const float* pixelcoords = (const float*)d_in[4];
    const float* volume      = (const float*)d_in[5];
    float* out = (float*)d_out;

    {
        long n = (long)BB * (D3 / 4);
        int threads = 256;
        int blocks = (int)((n + threads - 1) / threads);
        interleave_kernel<<<blocks, threads>>>((const float4*)volume, volume);
    }
    {
        dim3 block(8, 16, 1);   // warp = 8x4 pixel tile (tight ray bundles)
        dim3 grid(WW / 8, HH / 16, BB);
        raymarch_kernel<<<grid, block>>>(camrot, campos, focal, princpt,
                                         pixelcoords, out);
    }
}

// round 7
// speedup vs baseline: 1.2880x; 1.1595x over previous
#include <cuda_runtime.h>
#include <cuda_fp16.h>
#include <math.h>

// Problem constants (from reference setup_inputs)
#define BB 2
#define HH 256
#define WW 256
#define DD 128
#define D3 (DD * DD * DD)
#define DT 0.03125f
#define NSTEPS 111

// Dual-parity half4-interleaved volume copies. Each uint4 entry = 2 voxels
// x 4 channels in fp16: (r0,g0),(b0,a0),(r1,g1),(b1,a1).
//  g_volA entry i = voxels (2i, 2i+1)   -> even x0 pairs
//  g_volB entry i = voxels (2i+1, 2i+2) -> odd  x0 pairs (entry 63 of each
//                   row is padding, never read since x0 <= 126)
__device__ uint4 g_volA[BB * D3 / 2];
__device__ uint4 g_volB[BB * D3 / 2];

__device__ __forceinline__ unsigned pack2h(float lo, float hi) {
    __half2 h = __floats2half2_rn(lo, hi);
    return *reinterpret_cast<unsigned*>(&h);
}

__device__ __forceinline__ uint4 pack8h(float r0, float g0, float b0, float a0,
                                        float r1, float g1, float b1, float a1) {
    uint4 u;
    u.x = pack2h(r0, g0);
    u.y = pack2h(b0, a0);
    u.z = pack2h(r1, g1);
    u.w = pack2h(b1, a1);
    return u;
}

// ---------------------------------------------------------------------------
// Pass 1: interleave + fp16-pack. Each thread handles 4 voxels; the
// straddling "next voxel" for copy B comes from lane+1 via shuffle
// (gmem fallback only on warp/array boundary).
// ---------------------------------------------------------------------------
__global__ void interleave_kernel(const float4* __restrict__ vol4,
                                  const float* __restrict__ vol) {
    const int QP = D3 / 4;
    long i = (long)blockIdx.x * blockDim.x + threadIdx.x;
    if (i >= (long)BB * QP) return;
    int b = (int)(i / QP);
    int s4 = (int)(i % QP);
    const float4* base4 = vol4 + (long)b * 4 * QP;
    float4 c0 = __ldg(base4 + 0 * QP + s4);
    float4 c1 = __ldg(base4 + 1 * QP + s4);
    float4 c2 = __ldg(base4 + 2 * QP + s4);
    float4 c3 = __ldg(base4 + 3 * QP + s4);

    // next voxel (4*s4+4) channel values: lane+1's (c0.x,c1.x,c2.x,c3.x)
    int lane = threadIdx.x & 31;
    float n0 = __shfl_down_sync(0xffffffffu, c0.x, 1);
    float n1 = __shfl_down_sync(0xffffffffu, c1.x, 1);
    float n2 = __shfl_down_sync(0xffffffffu, c2.x, 1);
    float n3 = __shfl_down_sync(0xffffffffu, c3.x, 1);
    if (lane == 31 || s4 == QP - 1) {  // warp or array boundary: gmem
        int vn = min(s4 * 4 + 4, D3 - 1);
        const float* basef = vol + (long)b * 4 * D3;
        n0 = __ldg(basef + 0 * D3 + vn);
        n1 = __ldg(basef + 1 * D3 + vn);
        n2 = __ldg(basef + 2 * D3 + vn);
        n3 = __ldg(basef + 3 * D3 + vn);
    }

    long o = (long)b * (D3 / 2) + (long)s4 * 2;
    g_volA[o + 0] = pack8h(c0.x, c1.x, c2.x, c3.x, c0.y, c1.y, c2.y, c3.y);
    g_volA[o + 1] = pack8h(c0.z, c1.z, c2.z, c3.z, c0.w, c1.w, c2.w, c3.w);
    g_volB[o + 0] = pack8h(c0.y, c1.y, c2.y, c3.y, c0.z, c1.z, c2.z, c3.z);
    g_volB[o + 1] = pack8h(c0.w, c1.w, c2.w, c3.w, n0, n1, n2, n3);
}

// One pipeline stage: validity, fractions, 4 in-flight corner-pair loads.
struct Stage {
    bool valid;
    float fx, fy, fz;
    uint4 U00, U01, U10, U11;
};

__device__ __forceinline__ void prep_step(
    const uint4* __restrict__ vbA, const uint4* __restrict__ vbB,
    float pxp, float pyp, float pzp, Stage& st) {
    // valid  <=>  (-1 < p < 1) on all axes  <=>  max|p| < 1   (exact)
    float m = fmaxf(fmaxf(fabsf(pxp), fabsf(pyp)), fabsf(pzp));
    st.valid = m < 1.0f;
    float gx = fmaf(pxp, 63.5f, 63.5f);
    float gy = fmaf(pyp, 63.5f, 63.5f);
    float gz = fmaf(pzp, 63.5f, 63.5f);
    int x0 = min(max(__float2int_rd(gx), 0), DD - 2);
    int y0 = min(max(__float2int_rd(gy), 0), DD - 2);
    int z0 = min(max(__float2int_rd(gz), 0), DD - 2);
    st.fx = gx - (float)x0;
    st.fy = gy - (float)y0;
    st.fz = gz - (float)z0;
    const uint4* __restrict__ volp = (x0 & 1) ? vbB : vbA;
    int base = (((z0 << 7) + y0) << 6) + (x0 >> 1);
    st.U00 = __ldg(volp + base);
    st.U01 = __ldg(volp + base + 64);              // y+1
    st.U10 = __ldg(volp + base + 64 * 128);        // z+1
    st.U11 = __ldg(volp + base + 64 * 128 + 64);   // z+1,y+1
}

// Accumulate a corner pair (weights w0 for left voxel, w1 for right)
__device__ __forceinline__ void acc_pair(uint4 U, float w0, float w1,
                                         float& s0, float& s1,
                                         float& s2, float& s3) {
    float2 rg0 = __half22float2(*reinterpret_cast<const __half2*>(&U.x));
    float2 ba0 = __half22float2(*reinterpret_cast<const __half2*>(&U.y));
    float2 rg1 = __half22float2(*reinterpret_cast<const __half2*>(&U.z));
    float2 ba1 = __half22float2(*reinterpret_cast<const __half2*>(&U.w));
    s0 = fmaf(w0, rg0.x, s0); s1 = fmaf(w0, rg0.y, s1);
    s2 = fmaf(w0, ba0.x, s2); s3 = fmaf(w0, ba0.y, s3);
    s0 = fmaf(w1, rg1.x, s0); s1 = fmaf(w1, rg1.y, s1);
    s2 = fmaf(w1, ba1.x, s2); s3 = fmaf(w1, ba1.y, s3);
}

// Consume a stage: trilerp + bit-exact compositing. Returns true if alpha
// saturated (exactly 1.0 -> all future contributions are exactly 0).
__device__ __forceinline__ bool consume(const Stage& st,
                                        float& r_out, float& g_out,
                                        float& b_out, float& a_out) {
    if (!st.valid) return false;
    float wx0 = 1.0f - st.fx;
    float w00 = (1.0f - st.fz) * (1.0f - st.fy);
    float w01 = (1.0f - st.fz) * st.fy;
    float w10 = st.fz * (1.0f - st.fy);
    float w11 = st.fz * st.fy;

    float s0 = 0.0f, s1 = 0.0f, s2 = 0.0f, s3 = 0.0f;
    acc_pair(st.U00, w00 * wx0, w00 * st.fx, s0, s1, s2, s3);
    acc_pair(st.U01, w01 * wx0, w01 * st.fx, s0, s1, s2, s3);
    acc_pair(st.U10, w10 * wx0, w10 * st.fx, s0, s1, s2, s3);
    acc_pair(st.U11, w11 * wx0, w11 * st.fx, s0, s1, s2, s3);

    float contrib = __fsub_rn(
        fminf(__fadd_rn(a_out, __fmul_rn(s3, DT)), 1.0f), a_out);
    r_out = __fadd_rn(r_out, __fmul_rn(s0, contrib));
    g_out = __fadd_rn(g_out, __fmul_rn(s1, contrib));
    b_out = __fadd_rn(b_out, __fmul_rn(s2, contrib));
    a_out = __fadd_rn(a_out, contrib);
    return a_out >= 1.0f;
}

// ---------------------------------------------------------------------------
// Pass 2: ray march, depth-1 prefetch with ping-pong stages (no rotation
// moves). One thread per pixel, warp covers an 8x4 pixel tile. Ray setup +
// position stepping replicate the reference's IEEE fp32 ops bit-exactly
// (unfused _rn intrinsics): step-0 validity is a knife-edge (entry position
// lies exactly on the cube face). Downstream of a valid position everything
// is smooth. Phantom steps past kmax are geometrically invalid by a margin
// far above fp drift, so their valid-gate is false.
// ---------------------------------------------------------------------------
__global__ void __launch_bounds__(128, 7)
raymarch_kernel(const float* __restrict__ camrot,
                const float* __restrict__ campos,
                const float* __restrict__ focal,
                const float* __restrict__ princpt,
                const float* __restrict__ pixelcoords,
                float* __restrict__ out) {
    int x = blockIdx.x * blockDim.x + threadIdx.x;
    int y = blockIdx.y * blockDim.y + threadIdx.y;
    int b = blockIdx.z;

    // --- camera ray (bit-exact vs reference) ---
    long pidx = (((long)b * HH + y) * WW + x) * 2;
    float px = pixelcoords[pidx + 0];
    float py = pixelcoords[pidx + 1];
    float rx = __fdiv_rn(__fsub_rn(px, princpt[b * 2 + 0]), focal[b * 2 + 0]);
    float ry = __fdiv_rn(__fsub_rn(py, princpt[b * 2 + 1]), focal[b * 2 + 1]);
    float rz = 1.0f;
    const float* R = camrot + b * 9;  // dir_j = sum_i R[i][j] * r_i
    float dx = __fadd_rn(__fadd_rn(__fmul_rn(R[0], rx), __fmul_rn(R[3], ry)),
                         __fmul_rn(R[6], rz));
    float dy = __fadd_rn(__fadd_rn(__fmul_rn(R[1], rx), __fmul_rn(R[4], ry)),
                         __fmul_rn(R[7], rz));
    float dz = __fadd_rn(__fadd_rn(__fmul_rn(R[2], rx), __fmul_rn(R[5], ry)),
                         __fmul_rn(R[8], rz));
    float n2 = __fadd_rn(__fadd_rn(__fmul_rn(dx, dx), __fmul_rn(dy, dy)),
                         __fmul_rn(dz, dz));
    float nrm = sqrtf(n2);
    dx = __fdiv_rn(dx, nrm);
    dy = __fdiv_rn(dy, nrm);
    dz = __fdiv_rn(dz, nrm);

    float cx = campos[b * 3 + 0];
    float cy = campos[b * 3 + 1];
    float cz = campos[b * 3 + 2];

    // --- AABB [-1,1]^3 intersection (IEEE divisions; inf semantics ok) ---
    float t1x = __fdiv_rn(__fsub_rn(-1.0f, cx), dx);
    float t2x = __fdiv_rn(__fsub_rn( 1.0f, cx), dx);
    float t1y = __fdiv_rn(__fsub_rn(-1.0f, cy), dy);
    float t2y = __fdiv_rn(__fsub_rn( 1.0f, cy), dy);
    float t1z = __fdiv_rn(__fsub_rn(-1.0f, cz), dz);
    float t2z = __fdiv_rn(__fsub_rn( 1.0f, cz), dz);
    float tmin = fmaxf(fminf(t1x, t2x), fmaxf(fminf(t1y, t2y), fminf(t1z, t2z)));
    float tmax = fminf(fmaxf(t1x, t2x), fminf(fmaxf(t1y, t2y), fmaxf(t1z, t2z)));
    bool hit = tmin < tmax;
    float t0 = fmaxf(hit ? tmin : 0.0f, 0.0f);

    // raypos = campos + raydir * t0 (unfused, matches reference rounding)
    float posx = __fadd_rn(cx, __fmul_rn(dx, t0));
    float posy = __fadd_rn(cy, __fmul_rn(dy, t0));
    float posz = __fadd_rn(cz, __fmul_rn(dz, t0));

    // per-step increment raydir*DT (reference recomputes; same rounded value)
    float sx = __fmul_rn(dx, DT);
    float sy = __fmul_rn(dy, DT);
    float sz = __fmul_rn(dz, DT);

    float r_out = 0.0f, g_out = 0.0f, b_out = 0.0f, a_out = 0.0f;

    if (hit) {
        const uint4* __restrict__ vbA = g_volA + (long)b * (D3 / 2);
        const uint4* __restrict__ vbB = g_volB + (long)b * (D3 / 2);
        // steps beyond kmax are geometrically invalid (validated R4/R5)
        int kmax = (int)((tmax - t0) * 32.0f) + 3;
        if (kmax > NSTEPS) kmax = NSTEPS;

        Stage stA, stB;
        prep_step(vbA, vbB, posx, posy, posz, stA);

        #pragma unroll 1
        for (int k = 0; k < kmax; k += 2) {
            // advance (exact chain) + prefetch step k+1 into stage B
            posx = __fadd_rn(posx, sx);
            posy = __fadd_rn(posy, sy);
            posz = __fadd_rn(posz, sz);
            prep_step(vbA, vbB, posx, posy, posz, stB);
            // consume step k
            if (consume(stA, r_out, g_out, b_out, a_out)) break;

            // advance + prefetch step k+2 into stage A
            posx = __fadd_rn(posx, sx);
            posy = __fadd_rn(posy, sy);
            posz = __fadd_rn(posz, sz);
            prep_step(vbA, vbB, posx, posy, posz, stA);
            // consume step k+1 (may be a phantom step if kmax odd: its
            // valid-gate is false by geometric margin, contributes nothing)
            if (consume(stB, r_out, g_out, b_out, a_out)) break;
        }
    }

    long obase = (((long)b * 4) * HH + y) * WW + x;
    const long cstride = (long)HH * WW;
    out[obase + 0 * cstride] = r_out;
    out[obase + 1 * cstride] = g_out;
    out[obase + 2 * cstride] = b_out;
    out[obase + 3 * cstride] = a_out;
}

extern "C" void kernel_launch(void* const* d_in, const int* in_sizes, int n_in,
                              void* d_out, int out_size) {
    const float* camrot      = (const float*)d_in[0];
    const float* campos      = (const float*)d_in[1];
    const float* focal       = (const float*)d_in[2];
    const float* princpt     = (const float*)d_in[3];
    const float* pixelcoords = (const float*)d_in[4];
    const float* volume      = (const float*)d_in[5];
    float* out = (float*)d_out;

    {
        long n = (long)BB * (D3 / 4);
        int threads = 256;
        int blocks = (int)((n + threads - 1) / threads);
        interleave_kernel<<<blocks, threads>>>((const float4*)volume, volume);
    }
    {
        dim3 block(8, 16, 1);   // warp = 8x4 pixel tile (tight ray bundles)
        dim3 grid(WW / 8, HH / 16, BB);
        raymarch_kernel<<<grid, block>>>(camrot, campos, focal, princpt,
                                         pixelcoords, out);
    }
}

// round 8
// speedup vs baseline: 1.3709x; 1.0644x over previous
#include <cuda_runtime.h>
#include <cuda_fp16.h>
#include <math.h>

// Problem constants (from reference setup_inputs)
#define BB 2
#define HH 256
#define WW 256
#define DD 128
#define D3 (DD * DD * DD)
#define DT 0.03125f
#define NSTEPS 111

// Dual-parity half4-interleaved volume copies. Each uint4 entry = 2 voxels
// x 4 channels in fp16: (r0,g0),(b0,a0),(r1,g1),(b1,a1).
//  g_volA entry i = voxels (2i, 2i+1)   -> even x0 pairs
//  g_volB entry i = voxels (2i+1, 2i+2) -> odd  x0 pairs (entry 63 of each
//                   row is padding, never read since x0 <= 126)
__device__ uint4 g_volA[BB * D3 / 2];
__device__ uint4 g_volB[BB * D3 / 2];

__device__ __forceinline__ unsigned pack2h(float lo, float hi) {
    __half2 h = __floats2half2_rn(lo, hi);
    return *reinterpret_cast<unsigned*>(&h);
}

__device__ __forceinline__ uint4 pack8h(float r0, float g0, float b0, float a0,
                                        float r1, float g1, float b1, float a1) {
    uint4 u;
    u.x = pack2h(r0, g0);
    u.y = pack2h(b0, a0);
    u.z = pack2h(r1, g1);
    u.w = pack2h(b1, a1);
    return u;
}

// ---------------------------------------------------------------------------
// Pass 1: interleave + fp16-pack. Each thread handles 4 voxels; the
// straddling "next voxel" for copy B comes from lane+1 via shuffle
// (gmem fallback only on warp/array boundary).
// ---------------------------------------------------------------------------
__global__ void interleave_kernel(const float4* __restrict__ vol4,
                                  const float* __restrict__ vol) {
    const int QP = D3 / 4;
    long i = (long)blockIdx.x * blockDim.x + threadIdx.x;
    if (i >= (long)BB * QP) return;
    int b = (int)(i / QP);
    int s4 = (int)(i % QP);
    const float4* base4 = vol4 + (long)b * 4 * QP;
    float4 c0 = __ldg(base4 + 0 * QP + s4);
    float4 c1 = __ldg(base4 + 1 * QP + s4);
    float4 c2 = __ldg(base4 + 2 * QP + s4);
    float4 c3 = __ldg(base4 + 3 * QP + s4);

    // next voxel (4*s4+4) channel values: lane+1's (c0.x,c1.x,c2.x,c3.x)
    int lane = threadIdx.x & 31;
    float n0 = __shfl_down_sync(0xffffffffu, c0.x, 1);
    float n1 = __shfl_down_sync(0xffffffffu, c1.x, 1);
    float n2 = __shfl_down_sync(0xffffffffu, c2.x, 1);
    float n3 = __shfl_down_sync(0xffffffffu, c3.x, 1);
    if (lane == 31 || s4 == QP - 1) {  // warp or array boundary: gmem
        int vn = min(s4 * 4 + 4, D3 - 1);
        const float* basef = vol + (long)b * 4 * D3;
        n0 = __ldg(basef + 0 * D3 + vn);
        n1 = __ldg(basef + 1 * D3 + vn);
        n2 = __ldg(basef + 2 * D3 + vn);
        n3 = __ldg(basef + 3 * D3 + vn);
    }

    long o = (long)b * (D3 / 2) + (long)s4 * 2;
    g_volA[o + 0] = pack8h(c0.x, c1.x, c2.x, c3.x, c0.y, c1.y, c2.y, c3.y);
    g_volA[o + 1] = pack8h(c0.z, c1.z, c2.z, c3.z, c0.w, c1.w, c2.w, c3.w);
    g_volB[o + 0] = pack8h(c0.y, c1.y, c2.y, c3.y, c0.z, c1.z, c2.z, c3.z);
    g_volB[o + 1] = pack8h(c0.w, c1.w, c2.w, c3.w, n0, n1, n2, n3);
}

// One pipeline stage: validity, fractions, 4 in-flight corner-pair loads.
struct Stage {
    bool valid;
    float fx, fy, fz;
    uint4 U00, U01, U10, U11;
};

__device__ __forceinline__ void prep_step(
    const uint4* __restrict__ vbA, const uint4* __restrict__ vbB,
    float pxp, float pyp, float pzp, Stage& st) {
    // valid  <=>  (-1 < p < 1) on all axes  <=>  max|p| < 1   (exact)
    float m = fmaxf(fmaxf(fabsf(pxp), fabsf(pyp)), fabsf(pzp));
    st.valid = m < 1.0f;
    float gx = fmaf(pxp, 63.5f, 63.5f);
    float gy = fmaf(pyp, 63.5f, 63.5f);
    float gz = fmaf(pzp, 63.5f, 63.5f);
    int x0 = min(max(__float2int_rd(gx), 0), DD - 2);
    int y0 = min(max(__float2int_rd(gy), 0), DD - 2);
    int z0 = min(max(__float2int_rd(gz), 0), DD - 2);
    st.fx = gx - (float)x0;
    st.fy = gy - (float)y0;
    st.fz = gz - (float)z0;
    const uint4* __restrict__ volp = (x0 & 1) ? vbB : vbA;
    int base = (((z0 << 7) + y0) << 6) + (x0 >> 1);
    st.U00 = __ldg(volp + base);
    st.U01 = __ldg(volp + base + 64);              // y+1
    st.U10 = __ldg(volp + base + 64 * 128);        // z+1
    st.U11 = __ldg(volp + base + 64 * 128 + 64);   // z+1,y+1
}

__device__ __forceinline__ __half2 h2_of(unsigned u) {
    return *reinterpret_cast<const __half2*>(&u);
}

// half2 lerp: a + t*(b-a)
__device__ __forceinline__ __half2 h2lerp(__half2 a, __half2 b, __half2 t) {
    return __hfma2(t, __hsub2(b, a), a);
}

// Consume a stage: fp16 lerp-tree trilerp (x, then y, then z — same tree
// shape as the reference) + bit-exact fp32 compositing. Returns true if
// alpha saturated (exactly 1.0 -> all future contributions exactly 0).
__device__ __forceinline__ bool consume(const Stage& st,
                                        float& r_out, float& g_out,
                                        float& b_out, float& a_out) {
    if (!st.valid) return false;
    __half2 fxh = __float2half2_rn(st.fx);
    __half2 fyh = __float2half2_rn(st.fy);
    __half2 fzh = __float2half2_rn(st.fz);

    // x-lerp within each loaded pair (rg and ba channels ride together)
    __half2 c00rg = h2lerp(h2_of(st.U00.x), h2_of(st.U00.z), fxh);
    __half2 c00ba = h2lerp(h2_of(st.U00.y), h2_of(st.U00.w), fxh);
    __half2 c01rg = h2lerp(h2_of(st.U01.x), h2_of(st.U01.z), fxh);
    __half2 c01ba = h2lerp(h2_of(st.U01.y), h2_of(st.U01.w), fxh);
    __half2 c10rg = h2lerp(h2_of(st.U10.x), h2_of(st.U10.z), fxh);
    __half2 c10ba = h2lerp(h2_of(st.U10.y), h2_of(st.U10.w), fxh);
    __half2 c11rg = h2lerp(h2_of(st.U11.x), h2_of(st.U11.z), fxh);
    __half2 c11ba = h2lerp(h2_of(st.U11.y), h2_of(st.U11.w), fxh);
    // y-lerp
    __half2 c0rg = h2lerp(c00rg, c01rg, fyh);
    __half2 c0ba = h2lerp(c00ba, c01ba, fyh);
    __half2 c1rg = h2lerp(c10rg, c11rg, fyh);
    __half2 c1ba = h2lerp(c10ba, c11ba, fyh);
    // z-lerp
    float2 rg = __half22float2(h2lerp(c0rg, c1rg, fzh));
    float2 ba = __half22float2(h2lerp(c0ba, c1ba, fzh));

    float contrib = __fsub_rn(
        fminf(__fadd_rn(a_out, __fmul_rn(ba.y, DT)), 1.0f), a_out);
    r_out = __fadd_rn(r_out, __fmul_rn(rg.x, contrib));
    g_out = __fadd_rn(g_out, __fmul_rn(rg.y, contrib));
    b_out = __fadd_rn(b_out, __fmul_rn(ba.x, contrib));
    a_out = __fadd_rn(a_out, contrib);
    return a_out >= 1.0f;
}

// ---------------------------------------------------------------------------
// Pass 2: ray march, depth-1 prefetch with ping-pong stages (no rotation
// moves). One thread per pixel, warp covers an 8x4 pixel tile. Ray setup +
// position stepping replicate the reference's IEEE fp32 ops bit-exactly
// (unfused _rn intrinsics): step-0 validity is a knife-edge (entry position
// lies exactly on the cube face). Downstream of a valid position everything
// is smooth. Phantom steps past kmax are geometrically invalid by a margin
// far above fp drift, so their valid-gate is false.
// ---------------------------------------------------------------------------
__global__ void __launch_bounds__(128, 7)
raymarch_kernel(const float* __restrict__ camrot,
                const float* __restrict__ campos,
                const float* __restrict__ focal,
                const float* __restrict__ princpt,
                const float* __restrict__ pixelcoords,
                float* __restrict__ out) {
    int x = blockIdx.x * blockDim.x + threadIdx.x;
    int y = blockIdx.y * blockDim.y + threadIdx.y;
    int b = blockIdx.z;

    // --- camera ray (bit-exact vs reference) ---
    long pidx = (((long)b * HH + y) * WW + x) * 2;
    float px = pixelcoords[pidx + 0];
    float py = pixelcoords[pidx + 1];
    float rx = __fdiv_rn(__fsub_rn(px, princpt[b * 2 + 0]), focal[b * 2 + 0]);
    float ry = __fdiv_rn(__fsub_rn(py, princpt[b * 2 + 1]), focal[b * 2 + 1]);
    float rz = 1.0f;
    const float* R = camrot + b * 9;  // dir_j = sum_i R[i][j] * r_i
    float dx = __fadd_rn(__fadd_rn(__fmul_rn(R[0], rx), __fmul_rn(R[3], ry)),
                         __fmul_rn(R[6], rz));
    float dy = __fadd_rn(__fadd_rn(__fmul_rn(R[1], rx), __fmul_rn(R[4], ry)),
                         __fmul_rn(R[7], rz));
    float dz = __fadd_rn(__fadd_rn(__fmul_rn(R[2], rx), __fmul_rn(R[5], ry)),
                         __fmul_rn(R[8], rz));
    float n2 = __fadd_rn(__fadd_rn(__fmul_rn(dx, dx), __fmul_rn(dy, dy)),
                         __fmul_rn(dz, dz));
    float nrm = sqrtf(n2);
    dx = __fdiv_rn(dx, nrm);
    dy = __fdiv_rn(dy, nrm);
    dz = __fdiv_rn(dz, nrm);

    float cx = campos[b * 3 + 0];
    float cy = campos[b * 3 + 1];
    float cz = campos[b * 3 + 2];

    // --- AABB [-1,1]^3 intersection (IEEE divisions; inf semantics ok) ---
    float t1x = __fdiv_rn(__fsub_rn(-1.0f, cx), dx);
    float t2x = __fdiv_rn(__fsub_rn( 1.0f, cx), dx);
    float t1y = __fdiv_rn(__fsub_rn(-1.0f, cy), dy);
    float t2y = __fdiv_rn(__fsub_rn( 1.0f, cy), dy);
    float t1z = __fdiv_rn(__fsub_rn(-1.0f, cz), dz);
    float t2z = __fdiv_rn(__fsub_rn( 1.0f, cz), dz);
    float tmin = fmaxf(fminf(t1x, t2x), fmaxf(fminf(t1y, t2y), fminf(t1z, t2z)));
    float tmax = fminf(fmaxf(t1x, t2x), fminf(fmaxf(t1y, t2y), fmaxf(t1z, t2z)));
    bool hit = tmin < tmax;
    float t0 = fmaxf(hit ? tmin : 0.0f, 0.0f);

    // raypos = campos + raydir * t0 (unfused, matches reference rounding)
    float posx = __fadd_rn(cx, __fmul_rn(dx, t0));
    float posy = __fadd_rn(cy, __fmul_rn(dy, t0));
    float posz = __fadd_rn(cz, __fmul_rn(dz, t0));

    // per-step increment raydir*DT (reference recomputes; same rounded value)
    float sx = __fmul_rn(dx, DT);
    float sy = __fmul_rn(dy, DT);
    float sz = __fmul_rn(dz, DT);

    float r_out = 0.0f, g_out = 0.0f, b_out = 0.0f, a_out = 0.0f;

    if (hit) {
        const uint4* __restrict__ vbA = g_volA + (long)b * (D3 / 2);
        const uint4* __restrict__ vbB = g_volB + (long)b * (D3 / 2);
        // steps beyond kmax are geometrically invalid (validated R4/R5)
        int kmax = (int)((tmax - t0) * 32.0f) + 3;
        if (kmax > NSTEPS) kmax = NSTEPS;

        Stage stA, stB;
        prep_step(vbA, vbB, posx, posy, posz, stA);

        #pragma unroll 1
        for (int k = 0; k < kmax; k += 2) {
            // advance (exact chain) + prefetch step k+1 into stage B
            posx = __fadd_rn(posx, sx);
            posy = __fadd_rn(posy, sy);
            posz = __fadd_rn(posz, sz);
            prep_step(vbA, vbB, posx, posy, posz, stB);
            // consume step k
            if (consume(stA, r_out, g_out, b_out, a_out)) break;

            // advance + prefetch step k+2 into stage A
            posx = __fadd_rn(posx, sx);
            posy = __fadd_rn(posy, sy);
            posz = __fadd_rn(posz, sz);
            prep_step(vbA, vbB, posx, posy, posz, stA);
            // consume step k+1 (may be a phantom step if kmax odd: its
            // valid-gate is false by geometric margin, contributes nothing)
            if (consume(stB, r_out, g_out, b_out, a_out)) break;
        }
    }

    long obase = (((long)b * 4) * HH + y) * WW + x;
    const long cstride = (long)HH * WW;
    out[obase + 0 * cstride] = r_out;
    out[obase + 1 * cstride] = g_out;
    out[obase + 2 * cstride] = b_out;
    out[obase + 3 * cstride] = a_out;
}

extern "C" void kernel_launch(void* const* d_in, const int* in_sizes, int n_in,
                              void* d_out, int out_size) {
    const float* camrot      = (const float*)d_in[0];
    const float* campos      = (const float*)d_in[1];
    const float* focal       = (const float*)d_in[2];
    const float* princpt     = (const float*)d_in[3];
    const float* pixelcoords = (const float*)d_in[4];
    const float* volume      = (const float*)d_in[5];
    float* out = (float*)d_out;

    {
        long n = (long)BB * (D3 / 4);
        int threads = 256;
        int blocks = (int)((n + threads - 1) / threads);
        interleave_kernel<<<blocks, threads>>>((const float4*)volume, volume);
    }
    {
        dim3 block(8, 16, 1);   // warp = 8x4 pixel tile (tight ray bundles)
        dim3 grid(WW / 8, HH / 16, BB);
        raymarch_kernel<<<grid, block>>>(camrot, campos, focal, princpt,
                                         pixelcoords, out);
    }
}

// round 9
// speedup vs baseline: 1.3849x; 1.0102x over previous
#include <cuda_runtime.h>
#include <cuda_fp16.h>
#include <math.h>

// Problem constants (from reference setup_inputs)
#define BB 2
#define HH 256
#define WW 256
#define DD 128
#define D3 (DD * DD * DD)
#define DT 0.03125f
#define NSTEPS 111

// Dual-parity half4-interleaved volume copies. Each uint4 entry = 2 voxels
// x 4 channels in fp16: (r0,g0),(b0,a0),(r1,g1),(b1,a1).
//  g_volA entry i = voxels (2i, 2i+1)   -> even x0 pairs
//  g_volB entry i = voxels (2i+1, 2i+2) -> odd  x0 pairs (entry 63 of each
//                   row is padding, never read since x0 <= 126)
__device__ uint4 g_volA[BB * D3 / 2];
__device__ uint4 g_volB[BB * D3 / 2];

__device__ __forceinline__ unsigned pack2h(float lo, float hi) {
    __half2 h = __floats2half2_rn(lo, hi);
    return *reinterpret_cast<unsigned*>(&h);
}

__device__ __forceinline__ uint4 pack8h(float r0, float g0, float b0, float a0,
                                        float r1, float g1, float b1, float a1) {
    uint4 u;
    u.x = pack2h(r0, g0);
    u.y = pack2h(b0, a0);
    u.z = pack2h(r1, g1);
    u.w = pack2h(b1, a1);
    return u;
}

// ---------------------------------------------------------------------------
// Pass 1: interleave + fp16-pack. Each thread handles 4 voxels; the
// straddling "next voxel" for copy B comes from lane+1 via shuffle
// (gmem fallback only on warp/array boundary).
// ---------------------------------------------------------------------------
__global__ void interleave_kernel(const float4* __restrict__ vol4,
                                  const float* __restrict__ vol) {
    const int QP = D3 / 4;
    long i = (long)blockIdx.x * blockDim.x + threadIdx.x;
    if (i >= (long)BB * QP) return;
    int b = (int)(i / QP);
    int s4 = (int)(i % QP);
    const float4* base4 = vol4 + (long)b * 4 * QP;
    float4 c0 = __ldg(base4 + 0 * QP + s4);
    float4 c1 = __ldg(base4 + 1 * QP + s4);
    float4 c2 = __ldg(base4 + 2 * QP + s4);
    float4 c3 = __ldg(base4 + 3 * QP + s4);

    // next voxel (4*s4+4) channel values: lane+1's (c0.x,c1.x,c2.x,c3.x)
    int lane = threadIdx.x & 31;
    float n0 = __shfl_down_sync(0xffffffffu, c0.x, 1);
    float n1 = __shfl_down_sync(0xffffffffu, c1.x, 1);
    float n2 = __shfl_down_sync(0xffffffffu, c2.x, 1);
    float n3 = __shfl_down_sync(0xffffffffu, c3.x, 1);
    if (lane == 31 || s4 == QP - 1) {  // warp or array boundary: gmem
        int vn = min(s4 * 4 + 4, D3 - 1);
        const float* basef = vol + (long)b * 4 * D3;
        n0 = __ldg(basef + 0 * D3 + vn);
        n1 = __ldg(basef + 1 * D3 + vn);
        n2 = __ldg(basef + 2 * D3 + vn);
        n3 = __ldg(basef + 3 * D3 + vn);
    }

    long o = (long)b * (D3 / 2) + (long)s4 * 2;
    g_volA[o + 0] = pack8h(c0.x, c1.x, c2.x, c3.x, c0.y, c1.y, c2.y, c3.y);
    g_volA[o + 1] = pack8h(c0.z, c1.z, c2.z, c3.z, c0.w, c1.w, c2.w, c3.w);
    g_volB[o + 0] = pack8h(c0.y, c1.y, c2.y, c3.y, c0.z, c1.z, c2.z, c3.z);
    g_volB[o + 1] = pack8h(c0.w, c1.w, c2.w, c3.w, n0, n1, n2, n3);
}

// One pipeline stage: validity, fractions, 4 in-flight corner-pair loads.
struct Stage {
    bool valid;
    float fx, fy, fz;
    uint4 U00, U01, U10, U11;
};

__device__ __forceinline__ void prep_step(
    const uint4* __restrict__ vbA, const uint4* __restrict__ vbB,
    float pxp, float pyp, float pzp, Stage& st) {
    // valid  <=>  (-1 < p < 1) on all axes  <=>  max|p| < 1   (exact)
    float m = fmaxf(fmaxf(fabsf(pxp), fabsf(pyp)), fabsf(pzp));
    st.valid = m < 1.0f;
    float gx = fmaf(pxp, 63.5f, 63.5f);
    float gy = fmaf(pyp, 63.5f, 63.5f);
    float gz = fmaf(pzp, 63.5f, 63.5f);
    int x0 = min(max(__float2int_rd(gx), 0), DD - 2);
    int y0 = min(max(__float2int_rd(gy), 0), DD - 2);
    int z0 = min(max(__float2int_rd(gz), 0), DD - 2);
    st.fx = gx - (float)x0;
    st.fy = gy - (float)y0;
    st.fz = gz - (float)z0;
    const uint4* __restrict__ volp = (x0 & 1) ? vbB : vbA;
    int base = (((z0 << 7) + y0) << 6) + (x0 >> 1);
    st.U00 = __ldg(volp + base);
    st.U01 = __ldg(volp + base + 64);              // y+1
    st.U10 = __ldg(volp + base + 64 * 128);        // z+1
    st.U11 = __ldg(volp + base + 64 * 128 + 64);   // z+1,y+1
}

__device__ __forceinline__ __half2 h2_of(unsigned u) {
    return *reinterpret_cast<const __half2*>(&u);
}

// half2 lerp: a + t*(b-a)
__device__ __forceinline__ __half2 h2lerp(__half2 a, __half2 b, __half2 t) {
    return __hfma2(t, __hsub2(b, a), a);
}

// Branchless consume: fp16 lerp-tree trilerp (x, then y, then z) + bit-exact
// fp32 compositing, with the contribution gated by the validity flag via a
// single select. When valid the arithmetic is bit-identical to the gated
// version; when invalid, adding exact zeros leaves accumulators unchanged
// (all sampled values finite: indices clamped, weights finite near bounds).
__device__ __forceinline__ void consume(const Stage& st,
                                        float& r_out, float& g_out,
                                        float& b_out, float& a_out) {
    __half2 fxh = __float2half2_rn(st.fx);
    __half2 fyh = __float2half2_rn(st.fy);
    __half2 fzh = __float2half2_rn(st.fz);

    // x-lerp within each loaded pair (rg and ba channels ride together)
    __half2 c00rg = h2lerp(h2_of(st.U00.x), h2_of(st.U00.z), fxh);
    __half2 c00ba = h2lerp(h2_of(st.U00.y), h2_of(st.U00.w), fxh);
    __half2 c01rg = h2lerp(h2_of(st.U01.x), h2_of(st.U01.z), fxh);
    __half2 c01ba = h2lerp(h2_of(st.U01.y), h2_of(st.U01.w), fxh);
    __half2 c10rg = h2lerp(h2_of(st.U10.x), h2_of(st.U10.z), fxh);
    __half2 c10ba = h2lerp(h2_of(st.U10.y), h2_of(st.U10.w), fxh);
    __half2 c11rg = h2lerp(h2_of(st.U11.x), h2_of(st.U11.z), fxh);
    __half2 c11ba = h2lerp(h2_of(st.U11.y), h2_of(st.U11.w), fxh);
    // y-lerp
    __half2 c0rg = h2lerp(c00rg, c01rg, fyh);
    __half2 c0ba = h2lerp(c00ba, c01ba, fyh);
    __half2 c1rg = h2lerp(c10rg, c11rg, fyh);
    __half2 c1ba = h2lerp(c10ba, c11ba, fyh);
    // z-lerp
    float2 rg = __half22float2(h2lerp(c0rg, c1rg, fzh));
    float2 ba = __half22float2(h2lerp(c0ba, c1ba, fzh));

    float contrib = __fsub_rn(
        fminf(__fadd_rn(a_out, __fmul_rn(ba.y, DT)), 1.0f), a_out);
    contrib = st.valid ? contrib : 0.0f;   // single select, no branch
    r_out = __fadd_rn(r_out, __fmul_rn(rg.x, contrib));
    g_out = __fadd_rn(g_out, __fmul_rn(rg.y, contrib));
    b_out = __fadd_rn(b_out, __fmul_rn(ba.x, contrib));
    a_out = __fadd_rn(a_out, contrib);
}

// ---------------------------------------------------------------------------
// Pass 2: ray march, depth-1 prefetch with ping-pong stages. One thread per
// pixel, warp covers an 8x4 pixel tile. Ray setup + position stepping
// replicate the reference's IEEE fp32 ops bit-exactly (unfused _rn
// intrinsics): step-0 validity is a knife-edge (entry position lies exactly
// on the cube face). Downstream of a valid position everything is smooth.
// Saturation is checked once per unrolled pair: after alpha reaches exactly
// 1.0, every later contribution is exactly 0, so deferring the break is
// bit-safe. Phantom steps past kmax are geometrically invalid by a margin
// far above fp drift, so their valid-gate is false.
// ---------------------------------------------------------------------------
__global__ void __launch_bounds__(128, 7)
raymarch_kernel(const float* __restrict__ camrot,
                const float* __restrict__ campos,
                const float* __restrict__ focal,
                const float* __restrict__ princpt,
                const float* __restrict__ pixelcoords,
                float* __restrict__ out) {
    int x = blockIdx.x * blockDim.x + threadIdx.x;
    int y = blockIdx.y * blockDim.y + threadIdx.y;
    int b = blockIdx.z;

    // --- camera ray (bit-exact vs reference) ---
    long pidx = (((long)b * HH + y) * WW + x) * 2;
    float px = pixelcoords[pidx + 0];
    float py = pixelcoords[pidx + 1];
    float rx = __fdiv_rn(__fsub_rn(px, princpt[b * 2 + 0]), focal[b * 2 + 0]);
    float ry = __fdiv_rn(__fsub_rn(py, princpt[b * 2 + 1]), focal[b * 2 + 1]);
    float rz = 1.0f;
    const float* R = camrot + b * 9;  // dir_j = sum_i R[i][j] * r_i
    float dx = __fadd_rn(__fadd_rn(__fmul_rn(R[0], rx), __fmul_rn(R[3], ry)),
                         __fmul_rn(R[6], rz));
    float dy = __fadd_rn(__fadd_rn(__fmul_rn(R[1], rx), __fmul_rn(R[4], ry)),
                         __fmul_rn(R[7], rz));
    float dz = __fadd_rn(__fadd_rn(__fmul_rn(R[2], rx), __fmul_rn(R[5], ry)),
                         __fmul_rn(R[8], rz));
    float n2 = __fadd_rn(__fadd_rn(__fmul_rn(dx, dx), __fmul_rn(dy, dy)),
                         __fmul_rn(dz, dz));
    float nrm = sqrtf(n2);
    dx = __fdiv_rn(dx, nrm);
    dy = __fdiv_rn(dy, nrm);
    dz = __fdiv_rn(dz, nrm);

    float cx = campos[b * 3 + 0];
    float cy = campos[b * 3 + 1];
    float cz = campos[b * 3 + 2];

    // --- AABB [-1,1]^3 intersection (IEEE divisions; inf semantics ok) ---
    float t1x = __fdiv_rn(__fsub_rn(-1.0f, cx), dx);
    float t2x = __fdiv_rn(__fsub_rn( 1.0f, cx), dx);
    float t1y = __fdiv_rn(__fsub_rn(-1.0f, cy), dy);
    float t2y = __fdiv_rn(__fsub_rn( 1.0f, cy), dy);
    float t1z = __fdiv_rn(__fsub_rn(-1.0f, cz), dz);
    float t2z = __fdiv_rn(__fsub_rn( 1.0f, cz), dz);
    float tmin = fmaxf(fminf(t1x, t2x), fmaxf(fminf(t1y, t2y), fminf(t1z, t2z)));
    float tmax = fminf(fmaxf(t1x, t2x), fminf(fmaxf(t1y, t2y), fmaxf(t1z, t2z)));
    bool hit = tmin < tmax;
    float t0 = fmaxf(hit ? tmin : 0.0f, 0.0f);

    // raypos = campos + raydir * t0 (unfused, matches reference rounding)
    float posx = __fadd_rn(cx, __fmul_rn(dx, t0));
    float posy = __fadd_rn(cy, __fmul_rn(dy, t0));
    float posz = __fadd_rn(cz, __fmul_rn(dz, t0));

    // per-step increment raydir*DT (reference recomputes; same rounded value)
    float sx = __fmul_rn(dx, DT);
    float sy = __fmul_rn(dy, DT);
    float sz = __fmul_rn(dz, DT);

    float r_out = 0.0f, g_out = 0.0f, b_out = 0.0f, a_out = 0.0f;

    if (hit) {
        const uint4* __restrict__ vbA = g_volA + (long)b * (D3 / 2);
        const uint4* __restrict__ vbB = g_volB + (long)b * (D3 / 2);
        // steps beyond kmax are geometrically invalid (validated R4/R5)
        int kmax = (int)((tmax - t0) * 32.0f) + 3;
        if (kmax > NSTEPS) kmax = NSTEPS;

        Stage stA, stB;
        prep_step(vbA, vbB, posx, posy, posz, stA);

        #pragma unroll 1
        for (int k = 0; k < kmax; k += 2) {
            // advance (exact chain) + prefetch step k+1 into stage B
            posx = __fadd_rn(posx, sx);
            posy = __fadd_rn(posy, sy);
            posz = __fadd_rn(posz, sz);
            prep_step(vbA, vbB, posx, posy, posz, stB);
            // consume step k (branchless)
            consume(stA, r_out, g_out, b_out, a_out);

            // advance + prefetch step k+2 into stage A
            posx = __fadd_rn(posx, sx);
            posy = __fadd_rn(posy, sy);
            posz = __fadd_rn(posz, sz);
            prep_step(vbA, vbB, posx, posy, posz, stA);
            // consume step k+1 (phantom steps have valid=false; if alpha
            // saturated at step k, this contrib is exactly 0)
            consume(stB, r_out, g_out, b_out, a_out);

            // saturated alpha is exactly 1.0 -> all future contribs 0
            if (a_out >= 1.0f) break;
        }
    }

    long obase = (((long)b * 4) * HH + y) * WW + x;
    const long cstride = (long)HH * WW;
    out[obase + 0 * cstride] = r_out;
    out[obase + 1 * cstride] = g_out;
    out[obase + 2 * cstride] = b_out;
    out[obase + 3 * cstride] = a_out;
}

extern "C" void kernel_launch(void* const* d_in, const int* in_sizes, int n_in,
                              void* d_out, int out_size) {
    const float* camrot      = (const float*)d_in[0];
    const float* campos      = (const float*)d_in[1];
    const float* focal       = (const float*)d_in[2];
    const float* princpt     = (const float*)d_in[3];
    const float* pixelcoords = (const float*)d_in[4];
    const float* volume      = (const float*)d_in[5];
    float* out = (float*)d_out;

    {
        long n = (long)BB * (D3 / 4);
        int threads = 256;
        int blocks = (int)((n + threads - 1) / threads);
        interleave_kernel<<<blocks, threads>>>((const float4*)volume, volume);
    }
    {
        dim3 block(8, 16, 1);   // warp = 8x4 pixel tile (tight ray bundles)
        dim3 grid(WW / 8, HH / 16, BB);
        raymarch_kernel<<<grid, block>>>(camrot, campos, focal, princpt,
                                         pixelcoords, out);
    }
}

// round 10
// speedup vs baseline: 1.3864x; 1.0011x over previous
#include <cuda_runtime.h>
#include <cuda_fp16.h>
#include <math.h>

// Problem constants (from reference setup_inputs)
#define BB 2
#define HH 256
#define WW 256
#define DD 128
#define D3 (DD * DD * DD)
#define DT 0.03125f
#define NSTEPS 111

// Unified overlapping-pair volume: entry i (16 B uint4) = voxels (i, i+1),
// each voxel 4 channels fp16: (r0,g0),(b0,a0),(r1,g1),(b1,a1).
// Any x0 in [0,126] loads its corner pair with ONE aligned LDG.128 at
// entry index x0 — no parity split, and x-adjacent lanes share cache lines.
// Entries at row ends (x=127) hold wrapped data and are never read.
__device__ uint4 g_vol[BB * D3];

__device__ __forceinline__ unsigned pack2h(float lo, float hi) {
    __half2 h = __floats2half2_rn(lo, hi);
    return *reinterpret_cast<unsigned*>(&h);
}

__device__ __forceinline__ uint4 pack8h(float r0, float g0, float b0, float a0,
                                        float r1, float g1, float b1, float a1) {
    uint4 u;
    u.x = pack2h(r0, g0);
    u.y = pack2h(b0, a0);
    u.z = pack2h(r1, g1);
    u.w = pack2h(b1, a1);
    return u;
}

// ---------------------------------------------------------------------------
// Pass 1: interleave + fp16-pack. Each thread handles 4 voxels; the
// straddling "next voxel" comes from lane+1 via shuffle (gmem fallback only
// on warp/array boundary).
// ---------------------------------------------------------------------------
__global__ void interleave_kernel(const float4* __restrict__ vol4,
                                  const float* __restrict__ vol) {
    const int QP = D3 / 4;
    long i = (long)blockIdx.x * blockDim.x + threadIdx.x;
    if (i >= (long)BB * QP) return;
    int b = (int)(i / QP);
    int s4 = (int)(i % QP);
    const float4* base4 = vol4 + (long)b * 4 * QP;
    float4 c0 = __ldg(base4 + 0 * QP + s4);
    float4 c1 = __ldg(base4 + 1 * QP + s4);
    float4 c2 = __ldg(base4 + 2 * QP + s4);
    float4 c3 = __ldg(base4 + 3 * QP + s4);

    // next voxel (4*s4+4) channel values: lane+1's (c0.x,c1.x,c2.x,c3.x)
    int lane = threadIdx.x & 31;
    float n0 = __shfl_down_sync(0xffffffffu, c0.x, 1);
    float n1 = __shfl_down_sync(0xffffffffu, c1.x, 1);
    float n2 = __shfl_down_sync(0xffffffffu, c2.x, 1);
    float n3 = __shfl_down_sync(0xffffffffu, c3.x, 1);
    if (lane == 31 || s4 == QP - 1) {  // warp or array boundary: gmem
        int vn = min(s4 * 4 + 4, D3 - 1);
        const float* basef = vol + (long)b * 4 * D3;
        n0 = __ldg(basef + 0 * D3 + vn);
        n1 = __ldg(basef + 1 * D3 + vn);
        n2 = __ldg(basef + 2 * D3 + vn);
        n3 = __ldg(basef + 3 * D3 + vn);
    }

    long o = (long)b * D3 + (long)s4 * 4;
    g_vol[o + 0] = pack8h(c0.x, c1.x, c2.x, c3.x, c0.y, c1.y, c2.y, c3.y);
    g_vol[o + 1] = pack8h(c0.y, c1.y, c2.y, c3.y, c0.z, c1.z, c2.z, c3.z);
    g_vol[o + 2] = pack8h(c0.z, c1.z, c2.z, c3.z, c0.w, c1.w, c2.w, c3.w);
    g_vol[o + 3] = pack8h(c0.w, c1.w, c2.w, c3.w, n0, n1, n2, n3);
}

// One pipeline stage: validity, fractions, 4 in-flight corner-pair loads.
struct Stage {
    bool valid;
    float fx, fy, fz;
    uint4 U00, U01, U10, U11;
};

__device__ __forceinline__ void prep_step(
    const uint4* __restrict__ vb,
    float pxp, float pyp, float pzp, Stage& st) {
    // valid  <=>  (-1 < p < 1) on all axes  <=>  max|p| < 1   (exact)
    float m = fmaxf(fmaxf(fabsf(pxp), fabsf(pyp)), fabsf(pzp));
    st.valid = m < 1.0f;
    float gx = fmaf(pxp, 63.5f, 63.5f);
    float gy = fmaf(pyp, 63.5f, 63.5f);
    float gz = fmaf(pzp, 63.5f, 63.5f);
    int x0 = min(max(__float2int_rd(gx), 0), DD - 2);
    int y0 = min(max(__float2int_rd(gy), 0), DD - 2);
    int z0 = min(max(__float2int_rd(gz), 0), DD - 2);
    st.fx = gx - (float)x0;
    st.fy = gy - (float)y0;
    st.fz = gz - (float)z0;
    int base = (((z0 << 7) + y0) << 7) + x0;
    st.U00 = __ldg(vb + base);
    st.U01 = __ldg(vb + base + DD);            // y+1
    st.U10 = __ldg(vb + base + DD * DD);       // z+1
    st.U11 = __ldg(vb + base + DD * DD + DD);  // z+1, y+1
}

__device__ __forceinline__ __half2 h2_of(unsigned u) {
    return *reinterpret_cast<const __half2*>(&u);
}

// half2 lerp: a + t*(b-a)
__device__ __forceinline__ __half2 h2lerp(__half2 a, __half2 b, __half2 t) {
    return __hfma2(t, __hsub2(b, a), a);
}

// Branchless consume: fp16 lerp-tree trilerp (x, then y, then z) + bit-exact
// fp32 compositing, with the contribution gated by the validity flag via a
// single select. When valid the arithmetic is bit-identical to the gated
// version; when invalid, adding exact zeros leaves accumulators unchanged
// (all sampled values finite: indices clamped, weights finite near bounds).
__device__ __forceinline__ void consume(const Stage& st,
                                        float& r_out, float& g_out,
                                        float& b_out, float& a_out) {
    __half2 fxh = __float2half2_rn(st.fx);
    __half2 fyh = __float2half2_rn(st.fy);
    __half2 fzh = __float2half2_rn(st.fz);

    // x-lerp within each loaded pair (rg and ba channels ride together)
    __half2 c00rg = h2lerp(h2_of(st.U00.x), h2_of(st.U00.z), fxh);
    __half2 c00ba = h2lerp(h2_of(st.U00.y), h2_of(st.U00.w), fxh);
    __half2 c01rg = h2lerp(h2_of(st.U01.x), h2_of(st.U01.z), fxh);
    __half2 c01ba = h2lerp(h2_of(st.U01.y), h2_of(st.U01.w), fxh);
    __half2 c10rg = h2lerp(h2_of(st.U10.x), h2_of(st.U10.z), fxh);
    __half2 c10ba = h2lerp(h2_of(st.U10.y), h2_of(st.U10.w), fxh);
    __half2 c11rg = h2lerp(h2_of(st.U11.x), h2_of(st.U11.z), fxh);
    __half2 c11ba = h2lerp(h2_of(st.U11.y), h2_of(st.U11.w), fxh);
    // y-lerp
    __half2 c0rg = h2lerp(c00rg, c01rg, fyh);
    __half2 c0ba = h2lerp(c00ba, c01ba, fyh);
    __half2 c1rg = h2lerp(c10rg, c11rg, fyh);
    __half2 c1ba = h2lerp(c10ba, c11ba, fyh);
    // z-lerp
    float2 rg = __half22float2(h2lerp(c0rg, c1rg, fzh));
    float2 ba = __half22float2(h2lerp(c0ba, c1ba, fzh));

    float contrib = __fsub_rn(
        fminf(__fadd_rn(a_out, __fmul_rn(ba.y, DT)), 1.0f), a_out);
    contrib = st.valid ? contrib : 0.0f;   // single select, no branch
    r_out = __fadd_rn(r_out, __fmul_rn(rg.x, contrib));
    g_out = __fadd_rn(g_out, __fmul_rn(rg.y, contrib));
    b_out = __fadd_rn(b_out, __fmul_rn(ba.x, contrib));
    a_out = __fadd_rn(a_out, contrib);
}

// ---------------------------------------------------------------------------
// Pass 2: ray march, depth-1 prefetch with ping-pong stages. One thread per
// pixel, warp covers an 8x4 pixel tile. Ray setup + position stepping
// replicate the reference's IEEE fp32 ops bit-exactly (unfused _rn
// intrinsics): step-0 validity is a knife-edge (entry position lies exactly
// on the cube face). Downstream of a valid position everything is smooth.
// Saturation is checked once per unrolled pair: after alpha reaches exactly
// 1.0, every later contribution is exactly 0, so deferring the break is
// bit-safe. Phantom steps past kmax are geometrically invalid by a margin
// far above fp drift, so their valid-gate is false.
// ---------------------------------------------------------------------------
__global__ void __launch_bounds__(128, 7)
raymarch_kernel(const float* __restrict__ camrot,
                const float* __restrict__ campos,
                const float* __restrict__ focal,
                const float* __restrict__ princpt,
                const float* __restrict__ pixelcoords,
                float* __restrict__ out) {
    int x = blockIdx.x * blockDim.x + threadIdx.x;
    int y = blockIdx.y * blockDim.y + threadIdx.y;
    int b = blockIdx.z;

    // --- camera ray (bit-exact vs reference) ---
    long pidx = (((long)b * HH + y) * WW + x) * 2;
    float px = pixelcoords[pidx + 0];
    float py = pixelcoords[pidx + 1];
    float rx = __fdiv_rn(__fsub_rn(px, princpt[b * 2 + 0]), focal[b * 2 + 0]);
    float ry = __fdiv_rn(__fsub_rn(py, princpt[b * 2 + 1]), focal[b * 2 + 1]);
    float rz = 1.0f;
    const float* R = camrot + b * 9;  // dir_j = sum_i R[i][j] * r_i
    float dx = __fadd_rn(__fadd_rn(__fmul_rn(R[0], rx), __fmul_rn(R[3], ry)),
                         __fmul_rn(R[6], rz));
    float dy = __fadd_rn(__fadd_rn(__fmul_rn(R[1], rx), __fmul_rn(R[4], ry)),
                         __fmul_rn(R[7], rz));
    float dz = __fadd_rn(__fadd_rn(__fmul_rn(R[2], rx), __fmul_rn(R[5], ry)),
                         __fmul_rn(R[8], rz));
    float n2 = __fadd_rn(__fadd_rn(__fmul_rn(dx, dx), __fmul_rn(dy, dy)),
                         __fmul_rn(dz, dz));
    float nrm = sqrtf(n2);
    dx = __fdiv_rn(dx, nrm);
    dy = __fdiv_rn(dy, nrm);
    dz = __fdiv_rn(dz, nrm);

    float cx = campos[b * 3 + 0];
    float cy = campos[b * 3 + 1];
    float cz = campos[b * 3 + 2];

    // --- AABB [-1,1]^3 intersection (IEEE divisions; inf semantics ok) ---
    float t1x = __fdiv_rn(__fsub_rn(-1.0f, cx), dx);
    float t2x = __fdiv_rn(__fsub_rn( 1.0f, cx), dx);
    float t1y = __fdiv_rn(__fsub_rn(-1.0f, cy), dy);
    float t2y = __fdiv_rn(__fsub_rn( 1.0f, cy), dy);
    float t1z = __fdiv_rn(__fsub_rn(-1.0f, cz), dz);
    float t2z = __fdiv_rn(__fsub_rn( 1.0f, cz), dz);
    float tmin = fmaxf(fminf(t1x, t2x), fmaxf(fminf(t1y, t2y), fminf(t1z, t2z)));
    float tmax = fminf(fmaxf(t1x, t2x), fminf(fmaxf(t1y, t2y), fmaxf(t1z, t2z)));
    bool hit = tmin < tmax;
    float t0 = fmaxf(hit ? tmin : 0.0f, 0.0f);

    // raypos = campos + raydir * t0 (unfused, matches reference rounding)
    float posx = __fadd_rn(cx, __fmul_rn(dx, t0));
    float posy = __fadd_rn(cy, __fmul_rn(dy, t0));
    float posz = __fadd_rn(cz, __fmul_rn(dz, t0));

    // per-step increment raydir*DT (reference recomputes; same rounded value)
    float sx = __fmul_rn(dx, DT);
    float sy = __fmul_rn(dy, DT);
    float sz = __fmul_rn(dz, DT);

    float r_out = 0.0f, g_out = 0.0f, b_out = 0.0f, a_out = 0.0f;

    if (hit) {
        const uint4* __restrict__ vb = g_vol + (long)b * D3;
        // steps beyond kmax are geometrically invalid (validated R4/R5)
        int kmax = (int)((tmax - t0) * 32.0f) + 3;
        if (kmax > NSTEPS) kmax = NSTEPS;

        Stage stA, stB;
        prep_step(vb, posx, posy, posz, stA);

        #pragma unroll 1
        for (int k = 0; k < kmax; k += 2) {
            // advance (exact chain) + prefetch step k+1 into stage B
            posx = __fadd_rn(posx, sx);
            posy = __fadd_rn(posy, sy);
            posz = __fadd_rn(posz, sz);
            prep_step(vb, posx, posy, posz, stB);
            // consume step k (branchless)
            consume(stA, r_out, g_out, b_out, a_out);

            // advance + prefetch step k+2 into stage A
            posx = __fadd_rn(posx, sx);
            posy = __fadd_rn(posy, sy);
            posz = __fadd_rn(posz, sz);
            prep_step(vb, posx, posy, posz, stA);
            // consume step k+1 (phantom steps have valid=false; if alpha
            // saturated at step k, this contrib is exactly 0)
            consume(stB, r_out, g_out, b_out, a_out);

            // saturated alpha is exactly 1.0 -> all future contribs 0
            if (a_out >= 1.0f) break;
        }
    }

    long obase = (((long)b * 4) * HH + y) * WW + x;
    const long cstride = (long)HH * WW;
    out[obase + 0 * cstride] = r_out;
    out[obase + 1 * cstride] = g_out;
    out[obase + 2 * cstride] = b_out;
    out[obase + 3 * cstride] = a_out;
}

extern "C" void kernel_launch(void* const* d_in, const int* in_sizes, int n_in,
                              void* d_out, int out_size) {
    const float* camrot      = (const float*)d_in[0];
    const float* campos      = (const float*)d_in[1];
    const float* focal       = (const float*)d_in[2];
    const float* princpt     = (const float*)d_in[3];
    const float* pixelcoords = (const float*)d_in[4];
    const float* volume      = (const float*)d_in[5];
    float* out = (float*)d_out;

    {
        long n = (long)BB * (D3 / 4);
        int threads = 256;
        int blocks = (int)((n + threads - 1) / threads);
        interleave_kernel<<<blocks, threads>>>((const float4*)volume, volume);
    }
    {
        dim3 block(8, 16, 1);   // warp = 8x4 pixel tile (tight ray bundles)
        dim3 grid(WW / 8, HH / 16, BB);
        raymarch_kernel<<<grid, block>>>(camrot, campos, focal, princpt,
                                         pixelcoords, out);
    }
}

// round 11
// speedup vs baseline: 1.4248x; 1.0277x over previous
#include <cuda_runtime.h>
#include <cuda_fp16.h>
#include <math.h>

// Problem constants (from reference setup_inputs)
#define BB 2
#define HH 256
#define WW 256
#define DD 128
#define D3 (DD * DD * DD)
#define DT 0.03125f
#define NSTEPS 111

// Unified overlapping-pair volume: entry i (16 B uint4) = voxels (i, i+1),
// each voxel 4 channels fp16: (r0,g0),(b0,a0),(r1,g1),(b1,a1).
// Any x0 in [0,127] loads its corner pair with ONE aligned LDG.128.
// Padded by DD*DD+DD+1 zero-initialized entries so unclamped-neighbor
// addresses (x0/y0/z0 clamped to <=127 only) stay in bounds; such entries
// are only ever multiplied by exactly-zero weights.
__device__ uint4 g_vol[BB * D3 + DD * DD + DD + 1];

__device__ __forceinline__ unsigned pack2h(float lo, float hi) {
    __half2 h = __floats2half2_rn(lo, hi);
    return *reinterpret_cast<unsigned*>(&h);
}

__device__ __forceinline__ uint4 pack8h(float r0, float g0, float b0, float a0,
                                        float r1, float g1, float b1, float a1) {
    uint4 u;
    u.x = pack2h(r0, g0);
    u.y = pack2h(b0, a0);
    u.z = pack2h(r1, g1);
    u.w = pack2h(b1, a1);
    return u;
}

// ---------------------------------------------------------------------------
// Pass 1: interleave + fp16-pack. Each thread handles 4 voxels; the
// straddling "next voxel" comes from lane+1 via shuffle (gmem fallback only
// on warp/array boundary).
// ---------------------------------------------------------------------------
__global__ void interleave_kernel(const float4* __restrict__ vol4,
                                  const float* __restrict__ vol) {
    const int QP = D3 / 4;
    long i = (long)blockIdx.x * blockDim.x + threadIdx.x;
    if (i >= (long)BB * QP) return;
    int b = (int)(i / QP);
    int s4 = (int)(i % QP);
    const float4* base4 = vol4 + (long)b * 4 * QP;
    float4 c0 = __ldg(base4 + 0 * QP + s4);
    float4 c1 = __ldg(base4 + 1 * QP + s4);
    float4 c2 = __ldg(base4 + 2 * QP + s4);
    float4 c3 = __ldg(base4 + 3 * QP + s4);

    // next voxel (4*s4+4) channel values: lane+1's (c0.x,c1.x,c2.x,c3.x)
    int lane = threadIdx.x & 31;
    float n0 = __shfl_down_sync(0xffffffffu, c0.x, 1);
    float n1 = __shfl_down_sync(0xffffffffu, c1.x, 1);
    float n2 = __shfl_down_sync(0xffffffffu, c2.x, 1);
    float n3 = __shfl_down_sync(0xffffffffu, c3.x, 1);
    if (lane == 31 || s4 == QP - 1) {  // warp or array boundary: gmem
        int vn = min(s4 * 4 + 4, D3 - 1);
        const float* basef = vol + (long)b * 4 * D3;
        n0 = __ldg(basef + 0 * D3 + vn);
        n1 = __ldg(basef + 1 * D3 + vn);
        n2 = __ldg(basef + 2 * D3 + vn);
        n3 = __ldg(basef + 3 * D3 + vn);
    }

    long o = (long)b * D3 + (long)s4 * 4;
    g_vol[o + 0] = pack8h(c0.x, c1.x, c2.x, c3.x, c0.y, c1.y, c2.y, c3.y);
    g_vol[o + 1] = pack8h(c0.y, c1.y, c2.y, c3.y, c0.z, c1.z, c2.z, c3.z);
    g_vol[o + 2] = pack8h(c0.z, c1.z, c2.z, c3.z, c0.w, c1.w, c2.w, c3.w);
    g_vol[o + 3] = pack8h(c0.w, c1.w, c2.w, c3.w, n0, n1, n2, n3);
}

// One pipeline stage: validity, fractions, 4 in-flight corner-pair loads.
struct Stage {
    bool valid;
    float fx, fy, fz;
    uint4 U00, U01, U10, U11;
};

__device__ __forceinline__ void prep_step(
    const uint4* __restrict__ vb,
    float pxp, float pyp, float pzp, Stage& st) {
    // valid  <=>  (-1 < p < 1) on all axes  <=>  max|p| < 1   (exact)
    float m = fmaxf(fmaxf(fabsf(pxp), fabsf(pyp)), fabsf(pzp));
    st.valid = m < 1.0f;
    float gx = fmaf(pxp, 63.5f, 63.5f);
    float gy = fmaf(pyp, 63.5f, 63.5f);
    float gz = fmaf(pzp, 63.5f, 63.5f);
    // single unsigned clamp per axis: negative -> huge -> 127.
    // Valid positions give [0,127]; index 127 is only reachable with a
    // fraction of exactly 0, so the (wrapped/padded) neighbor entries are
    // multiplied by exactly-zero weights.
    int x0 = (int)min((unsigned)__float2int_rd(gx), 127u);
    int y0 = (int)min((unsigned)__float2int_rd(gy), 127u);
    int z0 = (int)min((unsigned)__float2int_rd(gz), 127u);
    st.fx = gx - (float)x0;
    st.fy = gy - (float)y0;
    st.fz = gz - (float)z0;
    int base = (((z0 << 7) + y0) << 7) + x0;
    st.U00 = __ldg(vb + base);
    st.U01 = __ldg(vb + base + DD);            // y+1
    st.U10 = __ldg(vb + base + DD * DD);       // z+1
    st.U11 = __ldg(vb + base + DD * DD + DD);  // z+1, y+1
}

__device__ __forceinline__ __half2 h2_of(unsigned u) {
    return *reinterpret_cast<const __half2*>(&u);
}

// half2 lerp: a + t*(b-a)
__device__ __forceinline__ __half2 h2lerp(__half2 a, __half2 b, __half2 t) {
    return __hfma2(t, __hsub2(b, a), a);
}

// Branchless consume: fp16 lerp-tree trilerp (x, then y, then z) + fp32
// compositing. The alpha chain is bit-exact unfused _rn (it gates
// saturation); rgb accumulators are smooth terminal outputs, so FFMA
// contraction there is harmless. Contribution gated by validity via one
// select; invalid steps add exact zeros.
__device__ __forceinline__ void consume(const Stage& st,
                                        float& r_out, float& g_out,
                                        float& b_out, float& a_out) {
    __half2 fxh = __float2half2_rn(st.fx);
    __half2 fyh = __float2half2_rn(st.fy);
    __half2 fzh = __float2half2_rn(st.fz);

    // x-lerp within each loaded pair (rg and ba channels ride together)
    __half2 c00rg = h2lerp(h2_of(st.U00.x), h2_of(st.U00.z), fxh);
    __half2 c00ba = h2lerp(h2_of(st.U00.y), h2_of(st.U00.w), fxh);
    __half2 c01rg = h2lerp(h2_of(st.U01.x), h2_of(st.U01.z), fxh);
    __half2 c01ba = h2lerp(h2_of(st.U01.y), h2_of(st.U01.w), fxh);
    __half2 c10rg = h2lerp(h2_of(st.U10.x), h2_of(st.U10.z), fxh);
    __half2 c10ba = h2lerp(h2_of(st.U10.y), h2_of(st.U10.w), fxh);
    __half2 c11rg = h2lerp(h2_of(st.U11.x), h2_of(st.U11.z), fxh);
    __half2 c11ba = h2lerp(h2_of(st.U11.y), h2_of(st.U11.w), fxh);
    // y-lerp
    __half2 c0rg = h2lerp(c00rg, c01rg, fyh);
    __half2 c0ba = h2lerp(c00ba, c01ba, fyh);
    __half2 c1rg = h2lerp(c10rg, c11rg, fyh);
    __half2 c1ba = h2lerp(c10ba, c11ba, fyh);
    // z-lerp
    float2 rg = __half22float2(h2lerp(c0rg, c1rg, fzh));
    float2 ba = __half22float2(h2lerp(c0ba, c1ba, fzh));

    float contrib = __fsub_rn(
        fminf(__fadd_rn(a_out, __fmul_rn(ba.y, DT)), 1.0f), a_out);
    contrib = st.valid ? contrib : 0.0f;   // single select, no branch
    r_out = fmaf(rg.x, contrib, r_out);    // smooth: FFMA ok
    g_out = fmaf(rg.y, contrib, g_out);
    b_out = fmaf(ba.x, contrib, b_out);
    a_out = __fadd_rn(a_out, contrib);     // exact: gates saturation
}

// ---------------------------------------------------------------------------
// Pass 2: ray march, depth-1 prefetch with ping-pong stages. One thread per
// pixel; 64-thread (8x8) blocks for fine-grained drain of variable-length
// rays. Ray setup + position stepping replicate the reference's IEEE fp32
// ops bit-exactly (unfused _rn intrinsics): step-0 validity is a knife-edge
// (entry position lies exactly on the cube face). Downstream of a valid
// position everything is smooth. Saturation is checked once per unrolled
// pair: after alpha reaches exactly 1.0 every later contribution is exactly
// 0, so deferring the break is bit-safe. Phantom steps past kmax are
// geometrically invalid by a margin far above fp drift.
// ---------------------------------------------------------------------------
__global__ void __launch_bounds__(64, 14)
raymarch_kernel(const float* __restrict__ camrot,
                const float* __restrict__ campos,
                const float* __restrict__ focal,
                const float* __restrict__ princpt,
                const float* __restrict__ pixelcoords,
                float* __restrict__ out) {
    int x = blockIdx.x * blockDim.x + threadIdx.x;
    int y = blockIdx.y * blockDim.y + threadIdx.y;
    int b = blockIdx.z;

    // --- camera ray (bit-exact vs reference) ---
    long pidx = (((long)b * HH + y) * WW + x) * 2;
    float px = pixelcoords[pidx + 0];
    float py = pixelcoords[pidx + 1];
    float rx = __fdiv_rn(__fsub_rn(px, princpt[b * 2 + 0]), focal[b * 2 + 0]);
    float ry = __fdiv_rn(__fsub_rn(py, princpt[b * 2 + 1]), focal[b * 2 + 1]);
    float rz = 1.0f;
    const float* R = camrot + b * 9;  // dir_j = sum_i R[i][j] * r_i
    float dx = __fadd_rn(__fadd_rn(__fmul_rn(R[0], rx), __fmul_rn(R[3], ry)),
                         __fmul_rn(R[6], rz));
    float dy = __fadd_rn(__fadd_rn(__fmul_rn(R[1], rx), __fmul_rn(R[4], ry)),
                         __fmul_rn(R[7], rz));
    float dz = __fadd_rn(__fadd_rn(__fmul_rn(R[2], rx), __fmul_rn(R[5], ry)),
                         __fmul_rn(R[8], rz));
    float n2 = __fadd_rn(__fadd_rn(__fmul_rn(dx, dx), __fmul_rn(dy, dy)),
                         __fmul_rn(dz, dz));
    float nrm = sqrtf(n2);
    dx = __fdiv_rn(dx, nrm);
    dy = __fdiv_rn(dy, nrm);
    dz = __fdiv_rn(dz, nrm);

    float cx = campos[b * 3 + 0];
    float cy = campos[b * 3 + 1];
    float cz = campos[b * 3 + 2];

    // --- AABB [-1,1]^3 intersection (IEEE divisions; inf semantics ok) ---
    float t1x = __fdiv_rn(__fsub_rn(-1.0f, cx), dx);
    float t2x = __fdiv_rn(__fsub_rn( 1.0f, cx), dx);
    float t1y = __fdiv_rn(__fsub_rn(-1.0f, cy), dy);
    float t2y = __fdiv_rn(__fsub_rn( 1.0f, cy), dy);
    float t1z = __fdiv_rn(__fsub_rn(-1.0f, cz), dz);
    float t2z = __fdiv_rn(__fsub_rn( 1.0f, cz), dz);
    float tmin = fmaxf(fminf(t1x, t2x), fmaxf(fminf(t1y, t2y), fminf(t1z, t2z)));
    float tmax = fminf(fmaxf(t1x, t2x), fminf(fmaxf(t1y, t2y), fmaxf(t1z, t2z)));
    bool hit = tmin < tmax;
    float t0 = fmaxf(hit ? tmin : 0.0f, 0.0f);

    // raypos = campos + raydir * t0 (unfused, matches reference rounding)
    float posx = __fadd_rn(cx, __fmul_rn(dx, t0));
    float posy = __fadd_rn(cy, __fmul_rn(dy, t0));
    float posz = __fadd_rn(cz, __fmul_rn(dz, t0));

    // per-step increment raydir*DT (reference recomputes; same rounded value)
    float sx = __fmul_rn(dx, DT);
    float sy = __fmul_rn(dy, DT);
    float sz = __fmul_rn(dz, DT);

    float r_out = 0.0f, g_out = 0.0f, b_out = 0.0f, a_out = 0.0f;

    if (hit) {
        const uint4* __restrict__ vb = g_vol + (long)b * D3;
        // steps beyond kmax are geometrically invalid (validated R4/R5)
        int kmax = (int)((tmax - t0) * 32.0f) + 3;
        if (kmax > NSTEPS) kmax = NSTEPS;

        Stage stA, stB;
        prep_step(vb, posx, posy, posz, stA);

        #pragma unroll 1
        for (int k = 0; k < kmax; k += 2) {
            // advance (exact chain) + prefetch step k+1 into stage B
            posx = __fadd_rn(posx, sx);
            posy = __fadd_rn(posy, sy);
            posz = __fadd_rn(posz, sz);
            prep_step(vb, posx, posy, posz, stB);
            // consume step k (branchless)
            consume(stA, r_out, g_out, b_out, a_out);

            // advance + prefetch step k+2 into stage A
            posx = __fadd_rn(posx, sx);
            posy = __fadd_rn(posy, sy);
            posz = __fadd_rn(posz, sz);
            prep_step(vb, posx, posy, posz, stA);
            // consume step k+1 (phantom steps have valid=false; if alpha
            // saturated at step k, this contrib is exactly 0)
            consume(stB, r_out, g_out, b_out, a_out);

            // saturated alpha is exactly 1.0 -> all future contribs 0
            if (a_out >= 1.0f) break;
        }
    }

    long obase = (((long)b * 4) * HH + y) * WW + x;
    const long cstride = (long)HH * WW;
    out[obase + 0 * cstride] = r_out;
    out[obase + 1 * cstride] = g_out;
    out[obase + 2 * cstride] = b_out;
    out[obase + 3 * cstride] = a_out;
}

extern "C" void kernel_launch(void* const* d_in, const int* in_sizes, int n_in,
                              void* d_out, int out_size) {
    const float* camrot      = (const float*)d_in[0];
    const float* campos      = (const float*)d_in[1];
    const float* focal       = (const float*)d_in[2];
    const float* princpt     = (const float*)d_in[3];
    const float* pixelcoords = (const float*)d_in[4];
    const float* volume      = (const float*)d_in[5];
    float* out = (float*)d_out;

    {
        long n = (long)BB * (D3 / 4);
        int threads = 256;
        int blocks = (int)((n + threads - 1) / threads);
        interleave_kernel<<<blocks, threads>>>((const float4*)volume, volume);
    }
    {
        dim3 block(8, 8, 1);    // warp = 8x4 pixels; fine-grained drain
        dim3 grid(WW / 8, HH / 8, BB);
        raymarch_kernel<<<grid, block>>>(camrot, campos, focal, princpt,
                                         pixelcoords, out);
    }
}

// round 12
// speedup vs baseline: 1.8103x; 1.2706x over previous
#include <cuda_runtime.h>
#include <cuda_fp16.h>
#include <math.h>

// Problem constants (from reference setup_inputs)
#define BB 2
#define HH 256
#define WW 256
#define DD 128
#define D3 (DD * DD * DD)
#define DT 0.03125f
#define NSTEPS 111

// Non-redundant half4 volume: entry i (8 B uint2) = voxel i's 4 channels in
// fp16: (r,g),(b,a). Corner loads are LDG.64; x-adjacent corners are
// contiguous. Padded by DD*DD+DD+1 zero-initialized entries so
// unclamped-neighbor addresses (x0/y0/z0 clamped to <=127 only) stay in
// bounds; such entries are only ever multiplied by exactly-zero weights.
__device__ uint2 g_vol[BB * D3 + DD * DD + DD + 1];

__device__ __forceinline__ unsigned pack2h(float lo, float hi) {
    __half2 h = __floats2half2_rn(lo, hi);
    return *reinterpret_cast<unsigned*>(&h);
}

// ---------------------------------------------------------------------------
// Pass 1: interleave + fp16-pack. Each thread packs 4 voxels (one float4 per
// channel) into two contiguous uint4 stores (4 x 8 B voxels).
// ---------------------------------------------------------------------------
__global__ void interleave_kernel(const float4* __restrict__ vol4) {
    const int QP = D3 / 4;
    long i = (long)blockIdx.x * blockDim.x + threadIdx.x;
    if (i >= (long)BB * QP) return;
    int b = (int)(i / QP);
    int s4 = (int)(i % QP);
    const float4* base4 = vol4 + (long)b * 4 * QP;
    float4 c0 = __ldg(base4 + 0 * QP + s4);
    float4 c1 = __ldg(base4 + 1 * QP + s4);
    float4 c2 = __ldg(base4 + 2 * QP + s4);
    float4 c3 = __ldg(base4 + 3 * QP + s4);

    uint4* outp = reinterpret_cast<uint4*>(g_vol) + ((long)b * D3 / 2 + (long)s4 * 2);
    uint4 u0, u1;
    u0.x = pack2h(c0.x, c1.x); u0.y = pack2h(c2.x, c3.x);   // voxel 4*s4+0
    u0.z = pack2h(c0.y, c1.y); u0.w = pack2h(c2.y, c3.y);   // voxel 4*s4+1
    u1.x = pack2h(c0.z, c1.z); u1.y = pack2h(c2.z, c3.z);   // voxel 4*s4+2
    u1.z = pack2h(c0.w, c1.w); u1.w = pack2h(c2.w, c3.w);   // voxel 4*s4+3
    outp[0] = u0;
    outp[1] = u1;
}

// One pipeline stage: validity, fractions, 8 in-flight corner loads.
struct Stage {
    bool valid;
    float fx, fy, fz;
    uint2 U000, U001, U010, U011, U100, U101, U110, U111;
};

__device__ __forceinline__ void prep_step(
    const uint2* __restrict__ vb,
    float pxp, float pyp, float pzp, Stage& st) {
    // valid  <=>  (-1 < p < 1) on all axes  <=>  max|p| < 1   (exact)
    float m = fmaxf(fmaxf(fabsf(pxp), fabsf(pyp)), fabsf(pzp));
    st.valid = m < 1.0f;
    float gx = fmaf(pxp, 63.5f, 63.5f);
    float gy = fmaf(pyp, 63.5f, 63.5f);
    float gz = fmaf(pzp, 63.5f, 63.5f);
    // single unsigned clamp per axis: negative -> huge -> 127.
    // Valid positions give [0,127]; index 127 is only reachable with a
    // fraction of exactly 0, so padded/neighbor entries are multiplied by
    // exactly-zero weights.
    int x0 = (int)min((unsigned)__float2int_rd(gx), 127u);
    int y0 = (int)min((unsigned)__float2int_rd(gy), 127u);
    int z0 = (int)min((unsigned)__float2int_rd(gz), 127u);
    st.fx = gx - (float)x0;
    st.fy = gy - (float)y0;
    st.fz = gz - (float)z0;
    int base = (((z0 << 7) + y0) << 7) + x0;
    st.U000 = __ldg(vb + base);
    st.U001 = __ldg(vb + base + 1);
    st.U010 = __ldg(vb + base + DD);
    st.U011 = __ldg(vb + base + DD + 1);
    st.U100 = __ldg(vb + base + DD * DD);
    st.U101 = __ldg(vb + base + DD * DD + 1);
    st.U110 = __ldg(vb + base + DD * DD + DD);
    st.U111 = __ldg(vb + base + DD * DD + DD + 1);
}

__device__ __forceinline__ __half2 h2_of(unsigned u) {
    return *reinterpret_cast<const __half2*>(&u);
}

// half2 lerp: a + t*(b-a)
__device__ __forceinline__ __half2 h2lerp(__half2 a, __half2 b, __half2 t) {
    return __hfma2(t, __hsub2(b, a), a);
}

// Branchless consume: fp16 lerp-tree trilerp (x, then y, then z) + fp32
// compositing. The alpha chain is bit-exact unfused _rn (it gates
// saturation); rgb accumulators are smooth terminal outputs, so FFMA
// contraction there is harmless. Contribution gated by validity via one
// select; invalid steps add exact zeros.
__device__ __forceinline__ void consume(const Stage& st,
                                        float& r_out, float& g_out,
                                        float& b_out, float& a_out) {
    __half2 fxh = __float2half2_rn(st.fx);
    __half2 fyh = __float2half2_rn(st.fy);
    __half2 fzh = __float2half2_rn(st.fz);

    // x-lerp between adjacent corner voxels (rg and ba ride together)
    __half2 c00rg = h2lerp(h2_of(st.U000.x), h2_of(st.U001.x), fxh);
    __half2 c00ba = h2lerp(h2_of(st.U000.y), h2_of(st.U001.y), fxh);
    __half2 c01rg = h2lerp(h2_of(st.U010.x), h2_of(st.U011.x), fxh);
    __half2 c01ba = h2lerp(h2_of(st.U010.y), h2_of(st.U011.y), fxh);
    __half2 c10rg = h2lerp(h2_of(st.U100.x), h2_of(st.U101.x), fxh);
    __half2 c10ba = h2lerp(h2_of(st.U100.y), h2_of(st.U101.y), fxh);
    __half2 c11rg = h2lerp(h2_of(st.U110.x), h2_of(st.U111.x), fxh);
    __half2 c11ba = h2lerp(h2_of(st.U110.y), h2_of(st.U111.y), fxh);
    // y-lerp
    __half2 c0rg = h2lerp(c00rg, c01rg, fyh);
    __half2 c0ba = h2lerp(c00ba, c01ba, fyh);
    __half2 c1rg = h2lerp(c10rg, c11rg, fyh);
    __half2 c1ba = h2lerp(c10ba, c11ba, fyh);
    // z-lerp
    float2 rg = __half22float2(h2lerp(c0rg, c1rg, fzh));
    float2 ba = __half22float2(h2lerp(c0ba, c1ba, fzh));

    float contrib = __fsub_rn(
        fminf(__fadd_rn(a_out, __fmul_rn(ba.y, DT)), 1.0f), a_out);
    contrib = st.valid ? contrib : 0.0f;   // single select, no branch
    r_out = fmaf(rg.x, contrib, r_out);    // smooth: FFMA ok
    g_out = fmaf(rg.y, contrib, g_out);
    b_out = fmaf(ba.x, contrib, b_out);
    a_out = __fadd_rn(a_out, contrib);     // exact: gates saturation
}

// ---------------------------------------------------------------------------
// Pass 2: ray march, depth-1 prefetch with ping-pong stages. One thread per
// pixel; 64-thread (8x8) blocks for fine-grained drain of variable-length
// rays. Ray setup + position stepping replicate the reference's IEEE fp32
// ops bit-exactly (unfused _rn intrinsics): step-0 validity is a knife-edge
// (entry position lies exactly on the cube face). Downstream of a valid
// position everything is smooth. Saturation is checked once per unrolled
// pair: after alpha reaches exactly 1.0 every later contribution is exactly
// 0, so deferring the break is bit-safe. Phantom steps past kmax are
// geometrically invalid by a margin far above fp drift.
// ---------------------------------------------------------------------------
__global__ void __launch_bounds__(64, 14)
raymarch_kernel(const float* __restrict__ camrot,
                const float* __restrict__ campos,
                const float* __restrict__ focal,
                const float* __restrict__ princpt,
                const float* __restrict__ pixelcoords,
                float* __restrict__ out) {
    int x = blockIdx.x * blockDim.x + threadIdx.x;
    int y = blockIdx.y * blockDim.y + threadIdx.y;
    int b = blockIdx.z;

    // --- camera ray (bit-exact vs reference) ---
    long pidx = (((long)b * HH + y) * WW + x) * 2;
    float px = pixelcoords[pidx + 0];
    float py = pixelcoords[pidx + 1];
    float rx = __fdiv_rn(__fsub_rn(px, princpt[b * 2 + 0]), focal[b * 2 + 0]);
    float ry = __fdiv_rn(__fsub_rn(py, princpt[b * 2 + 1]), focal[b * 2 + 1]);
    float rz = 1.0f;
    const float* R = camrot + b * 9;  // dir_j = sum_i R[i][j] * r_i
    float dx = __fadd_rn(__fadd_rn(__fmul_rn(R[0], rx), __fmul_rn(R[3], ry)),
                         __fmul_rn(R[6], rz));
    float dy = __fadd_rn(__fadd_rn(__fmul_rn(R[1], rx), __fmul_rn(R[4], ry)),
                         __fmul_rn(R[7], rz));
    float dz = __fadd_rn(__fadd_rn(__fmul_rn(R[2], rx), __fmul_rn(R[5], ry)),
                         __fmul_rn(R[8], rz));
    float n2 = __fadd_rn(__fadd_rn(__fmul_rn(dx, dx), __fmul_rn(dy, dy)),
                         __fmul_rn(dz, dz));
    float nrm = sqrtf(n2);
    dx = __fdiv_rn(dx, nrm);
    dy = __fdiv_rn(dy, nrm);
    dz = __fdiv_rn(dz, nrm);

    float cx = campos[b * 3 + 0];
    float cy = campos[b * 3 + 1];
    float cz = campos[b * 3 + 2];

    // --- AABB [-1,1]^3 intersection (IEEE divisions; inf semantics ok) ---
    float t1x = __fdiv_rn(__fsub_rn(-1.0f, cx), dx);
    float t2x = __fdiv_rn(__fsub_rn( 1.0f, cx), dx);
    float t1y = __fdiv_rn(__fsub_rn(-1.0f, cy), dy);
    float t2y = __fdiv_rn(__fsub_rn( 1.0f, cy), dy);
    float t1z = __fdiv_rn(__fsub_rn(-1.0f, cz), dz);
    float t2z = __fdiv_rn(__fsub_rn( 1.0f, cz), dz);
    float tmin = fmaxf(fminf(t1x, t2x), fmaxf(fminf(t1y, t2y), fminf(t1z, t2z)));
    float tmax = fminf(fmaxf(t1x, t2x), fminf(fmaxf(t1y, t2y), fmaxf(t1z, t2z)));
    bool hit = tmin < tmax;
    float t0 = fmaxf(hit ? tmin : 0.0f, 0.0f);

    // raypos = campos + raydir * t0 (unfused, matches reference rounding)
    float posx = __fadd_rn(cx, __fmul_rn(dx, t0));
    float posy = __fadd_rn(cy, __fmul_rn(dy, t0));
    float posz = __fadd_rn(cz, __fmul_rn(dz, t0));

    // per-step increment raydir*DT (reference recomputes; same rounded value)
    float sx = __fmul_rn(dx, DT);
    float sy = __fmul_rn(dy, DT);
    float sz = __fmul_rn(dz, DT);

    float r_out = 0.0f, g_out = 0.0f, b_out = 0.0f, a_out = 0.0f;

    if (hit) {
        const uint2* __restrict__ vb = g_vol + (long)b * D3;
        // steps beyond kmax are geometrically invalid (validated R4/R5)
        int kmax = (int)((tmax - t0) * 32.0f) + 3;
        if (kmax > NSTEPS) kmax = NSTEPS;

        Stage stA, stB;
        prep_step(vb, posx, posy, posz, stA);

        #pragma unroll 1
        for (int k = 0; k < kmax; k += 2) {
            // advance (exact chain) + prefetch step k+1 into stage B
            posx = __fadd_rn(posx, sx);
            posy = __fadd_rn(posy, sy);
            posz = __fadd_rn(posz, sz);
            prep_step(vb, posx, posy, posz, stB);
            // consume step k (branchless)
            consume(stA, r_out, g_out, b_out, a_out);

            // advance + prefetch step k+2 into stage A
            posx = __fadd_rn(posx, sx);
            posy = __fadd_rn(posy, sy);
            posz = __fadd_rn(posz, sz);
            prep_step(vb, posx, posy, posz, stA);
            // consume step k+1 (phantom steps have valid=false; if alpha
            // saturated at step k, this contrib is exactly 0)
            consume(stB, r_out, g_out, b_out, a_out);

            // saturated alpha is exactly 1.0 -> all future contribs 0
            if (a_out >= 1.0f) break;
        }
    }

    long obase = (((long)b * 4) * HH + y) * WW + x;
    const long cstride = (long)HH * WW;
    out[obase + 0 * cstride] = r_out;
    out[obase + 1 * cstride] = g_out;
    out[obase + 2 * cstride] = b_out;
    out[obase + 3 * cstride] = a_out;
}

extern "C" void kernel_launch(void* const* d_in, const int* in_sizes, int n_in,
                              void* d_out, int out_size) {
    const float* camrot      = (const float*)d_in[0];
    const float* campos      = (const float*)d_in[1];
    const float* focal       = (const float*)d_in[2];
    const float* princpt     = (const float*)d_in[3];
    const float* pixelcoords = (const float*)d_in[4];
    const float* volume      = (const float*)d_in[5];
    float* out = (float*)d_out;

    {
        long n = (long)BB * (D3 / 4);
        int threads = 256;
        int blocks = (int)((n + threads - 1) / threads);
        interleave_kernel<<<blocks, threads>>>((const float4*)volume);
    }
    {
        dim3 block(8, 8, 1);    // warp = 8x4 pixels; fine-grained drain
        dim3 grid(WW / 8, HH / 8, BB);
        raymarch_kernel<<<grid, block>>>(camrot, campos, focal, princpt,
                                         pixelcoords, out);
    }
}

// round 13
// speedup vs baseline: 1.8179x; 1.0042x over previous
#include <cuda_runtime.h>
#include <cuda_fp16.h>
#include <math.h>

// Problem constants (from reference setup_inputs)
#define BB 2
#define HH 256
#define WW 256
#define DD 128
#define D3 (DD * DD * DD)
#define DT 0.03125f
#define NSTEPS 111

// Non-redundant half4 volume: entry i (8 B uint2) = voxel i's 4 channels in
// fp16: (r,g),(b,a). Corner loads are LDG.64; x-adjacent corners are
// contiguous. Padded by DD*DD+DD+1 zero-initialized entries so
// unclamped-neighbor addresses (x0/y0/z0 clamped to <=127 only) stay in
// bounds; such entries are only ever multiplied by exactly-zero weights.
__device__ uint2 g_vol[BB * D3 + DD * DD + DD + 1];

__device__ __forceinline__ unsigned pack2h(float lo, float hi) {
    __half2 h = __floats2half2_rn(lo, hi);
    return *reinterpret_cast<unsigned*>(&h);
}

// ---------------------------------------------------------------------------
// Pass 1: interleave + fp16-pack ONE batch. Each thread packs 4 voxels (one
// float4 per channel) into two contiguous uint4 stores (4 x 8 B voxels).
// ---------------------------------------------------------------------------
__global__ void interleave_kernel(const float4* __restrict__ vol4, int b) {
    const int QP = D3 / 4;
    int s4 = blockIdx.x * blockDim.x + threadIdx.x;
    if (s4 >= QP) return;
    const float4* base4 = vol4 + (long)b * 4 * QP;
    float4 c0 = __ldg(base4 + 0 * QP + s4);
    float4 c1 = __ldg(base4 + 1 * QP + s4);
    float4 c2 = __ldg(base4 + 2 * QP + s4);
    float4 c3 = __ldg(base4 + 3 * QP + s4);

    uint4* outp = reinterpret_cast<uint4*>(g_vol) + ((long)b * D3 / 2 + (long)s4 * 2);
    uint4 u0, u1;
    u0.x = pack2h(c0.x, c1.x); u0.y = pack2h(c2.x, c3.x);   // voxel 4*s4+0
    u0.z = pack2h(c0.y, c1.y); u0.w = pack2h(c2.y, c3.y);   // voxel 4*s4+1
    u1.x = pack2h(c0.z, c1.z); u1.y = pack2h(c2.z, c3.z);   // voxel 4*s4+2
    u1.z = pack2h(c0.w, c1.w); u1.w = pack2h(c2.w, c3.w);   // voxel 4*s4+3
    outp[0] = u0;
    outp[1] = u1;
}

// One pipeline stage: validity, fractions, 8 in-flight corner loads.
struct Stage {
    bool valid;
    float fx, fy, fz;
    uint2 U000, U001, U010, U011, U100, U101, U110, U111;
};

__device__ __forceinline__ void prep_step(
    const uint2* __restrict__ vb,
    float pxp, float pyp, float pzp, Stage& st) {
    // valid  <=>  (-1 < p < 1) on all axes  <=>  max|p| < 1   (exact)
    float m = fmaxf(fmaxf(fabsf(pxp), fabsf(pyp)), fabsf(pzp));
    st.valid = m < 1.0f;
    float gx = fmaf(pxp, 63.5f, 63.5f);
    float gy = fmaf(pyp, 63.5f, 63.5f);
    float gz = fmaf(pzp, 63.5f, 63.5f);
    // single unsigned clamp per axis: negative -> huge -> 127.
    // Valid positions give [0,127]; index 127 is only reachable with a
    // fraction of exactly 0, so padded/neighbor entries are multiplied by
    // exactly-zero weights.
    int x0 = (int)min((unsigned)__float2int_rd(gx), 127u);
    int y0 = (int)min((unsigned)__float2int_rd(gy), 127u);
    int z0 = (int)min((unsigned)__float2int_rd(gz), 127u);
    st.fx = gx - (float)x0;
    st.fy = gy - (float)y0;
    st.fz = gz - (float)z0;
    int base = (((z0 << 7) + y0) << 7) + x0;
    st.U000 = __ldg(vb + base);
    st.U001 = __ldg(vb + base + 1);
    st.U010 = __ldg(vb + base + DD);
    st.U011 = __ldg(vb + base + DD + 1);
    st.U100 = __ldg(vb + base + DD * DD);
    st.U101 = __ldg(vb + base + DD * DD + 1);
    st.U110 = __ldg(vb + base + DD * DD + DD);
    st.U111 = __ldg(vb + base + DD * DD + DD + 1);
}

__device__ __forceinline__ __half2 h2_of(unsigned u) {
    return *reinterpret_cast<const __half2*>(&u);
}

// half2 lerp: a + t*(b-a)
__device__ __forceinline__ __half2 h2lerp(__half2 a, __half2 b, __half2 t) {
    return __hfma2(t, __hsub2(b, a), a);
}

// Branchless consume: fp16 lerp-tree trilerp (x, then y, then z) + fp32
// compositing. The alpha chain is bit-exact unfused _rn (it gates
// saturation); rgb accumulators are smooth terminal outputs, so FFMA
// contraction there is harmless. Contribution gated by validity via one
// select; invalid steps add exact zeros.
__device__ __forceinline__ void consume(const Stage& st,
                                        float& r_out, float& g_out,
                                        float& b_out, float& a_out) {
    __half2 fxh = __float2half2_rn(st.fx);
    __half2 fyh = __float2half2_rn(st.fy);
    __half2 fzh = __float2half2_rn(st.fz);

    // x-lerp between adjacent corner voxels (rg and ba ride together)
    __half2 c00rg = h2lerp(h2_of(st.U000.x), h2_of(st.U001.x), fxh);
    __half2 c00ba = h2lerp(h2_of(st.U000.y), h2_of(st.U001.y), fxh);
    __half2 c01rg = h2lerp(h2_of(st.U010.x), h2_of(st.U011.x), fxh);
    __half2 c01ba = h2lerp(h2_of(st.U010.y), h2_of(st.U011.y), fxh);
    __half2 c10rg = h2lerp(h2_of(st.U100.x), h2_of(st.U101.x), fxh);
    __half2 c10ba = h2lerp(h2_of(st.U100.y), h2_of(st.U101.y), fxh);
    __half2 c11rg = h2lerp(h2_of(st.U110.x), h2_of(st.U111.x), fxh);
    __half2 c11ba = h2lerp(h2_of(st.U110.y), h2_of(st.U111.y), fxh);
    // y-lerp
    __half2 c0rg = h2lerp(c00rg, c01rg, fyh);
    __half2 c0ba = h2lerp(c00ba, c01ba, fyh);
    __half2 c1rg = h2lerp(c10rg, c11rg, fyh);
    __half2 c1ba = h2lerp(c10ba, c11ba, fyh);
    // z-lerp
    float2 rg = __half22float2(h2lerp(c0rg, c1rg, fzh));
    float2 ba = __half22float2(h2lerp(c0ba, c1ba, fzh));

    float contrib = __fsub_rn(
        fminf(__fadd_rn(a_out, __fmul_rn(ba.y, DT)), 1.0f), a_out);
    contrib = st.valid ? contrib : 0.0f;   // single select, no branch
    r_out = fmaf(rg.x, contrib, r_out);    // smooth: FFMA ok
    g_out = fmaf(rg.y, contrib, g_out);
    b_out = fmaf(ba.x, contrib, b_out);
    a_out = __fadd_rn(a_out, contrib);     // exact: gates saturation
}

// ---------------------------------------------------------------------------
// Pass 2: ray march ONE batch, depth-1 prefetch with ping-pong stages.
// One thread per pixel; 64-thread (8x8) blocks for fine-grained drain of
// variable-length rays. Ray setup + position stepping replicate the
// reference's IEEE fp32 ops bit-exactly (unfused _rn intrinsics): step-0
// validity is a knife-edge (entry position lies exactly on the cube face).
// Downstream of a valid position everything is smooth. Saturation is checked
// once per unrolled pair: after alpha reaches exactly 1.0 every later
// contribution is exactly 0, so deferring the break is bit-safe. Phantom
// steps past kmax are geometrically invalid by a margin far above fp drift.
// ---------------------------------------------------------------------------
__global__ void __launch_bounds__(64, 14)
raymarch_kernel(const float* __restrict__ camrot,
                const float* __restrict__ campos,
                const float* __restrict__ focal,
                const float* __restrict__ princpt,
                const float* __restrict__ pixelcoords,
                float* __restrict__ out, int b) {
    int x = blockIdx.x * blockDim.x + threadIdx.x;
    int y = blockIdx.y * blockDim.y + threadIdx.y;

    // --- camera ray (bit-exact vs reference) ---
    long pidx = (((long)b * HH + y) * WW + x) * 2;
    float px = pixelcoords[pidx + 0];
    float py = pixelcoords[pidx + 1];
    float rx = __fdiv_rn(__fsub_rn(px, princpt[b * 2 + 0]), focal[b * 2 + 0]);
    float ry = __fdiv_rn(__fsub_rn(py, princpt[b * 2 + 1]), focal[b * 2 + 1]);
    float rz = 1.0f;
    const float* R = camrot + b * 9;  // dir_j = sum_i R[i][j] * r_i
    float dx = __fadd_rn(__fadd_rn(__fmul_rn(R[0], rx), __fmul_rn(R[3], ry)),
                         __fmul_rn(R[6], rz));
    float dy = __fadd_rn(__fadd_rn(__fmul_rn(R[1], rx), __fmul_rn(R[4], ry)),
                         __fmul_rn(R[7], rz));
    float dz = __fadd_rn(__fadd_rn(__fmul_rn(R[2], rx), __fmul_rn(R[5], ry)),
                         __fmul_rn(R[8], rz));
    float n2 = __fadd_rn(__fadd_rn(__fmul_rn(dx, dx), __fmul_rn(dy, dy)),
                         __fmul_rn(dz, dz));
    float nrm = sqrtf(n2);
    dx = __fdiv_rn(dx, nrm);
    dy = __fdiv_rn(dy, nrm);
    dz = __fdiv_rn(dz, nrm);

    float cx = campos[b * 3 + 0];
    float cy = campos[b * 3 + 1];
    float cz = campos[b * 3 + 2];

    // --- AABB [-1,1]^3 intersection (IEEE divisions; inf semantics ok) ---
    float t1x = __fdiv_rn(__fsub_rn(-1.0f, cx), dx);
    float t2x = __fdiv_rn(__fsub_rn( 1.0f, cx), dx);
    float t1y = __fdiv_rn(__fsub_rn(-1.0f, cy), dy);
    float t2y = __fdiv_rn(__fsub_rn( 1.0f, cy), dy);
    float t1z = __fdiv_rn(__fsub_rn(-1.0f, cz), dz);
    float t2z = __fdiv_rn(__fsub_rn( 1.0f, cz), dz);
    float tmin = fmaxf(fminf(t1x, t2x), fmaxf(fminf(t1y, t2y), fminf(t1z, t2z)));
    float tmax = fminf(fmaxf(t1x, t2x), fminf(fmaxf(t1y, t2y), fmaxf(t1z, t2z)));
    bool hit = tmin < tmax;
    float t0 = fmaxf(hit ? tmin : 0.0f, 0.0f);

    // raypos = campos + raydir * t0 (unfused, matches reference rounding)
    float posx = __fadd_rn(cx, __fmul_rn(dx, t0));
    float posy = __fadd_rn(cy, __fmul_rn(dy, t0));
    float posz = __fadd_rn(cz, __fmul_rn(dz, t0));

    // per-step increment raydir*DT (reference recomputes; same rounded value)
    float sx = __fmul_rn(dx, DT);
    float sy = __fmul_rn(dy, DT);
    float sz = __fmul_rn(dz, DT);

    float r_out = 0.0f, g_out = 0.0f, b_out = 0.0f, a_out = 0.0f;

    if (hit) {
        const uint2* __restrict__ vb = g_vol + (long)b * D3;
        // steps beyond kmax are geometrically invalid (validated R4/R5)
        int kmax = (int)((tmax - t0) * 32.0f) + 3;
        if (kmax > NSTEPS) kmax = NSTEPS;

        Stage stA, stB;
        prep_step(vb, posx, posy, posz, stA);

        #pragma unroll 1
        for (int k = 0; k < kmax; k += 2) {
            // advance (exact chain) + prefetch step k+1 into stage B
            posx = __fadd_rn(posx, sx);
            posy = __fadd_rn(posy, sy);
            posz = __fadd_rn(posz, sz);
            prep_step(vb, posx, posy, posz, stB);
            // consume step k (branchless)
            consume(stA, r_out, g_out, b_out, a_out);

            // advance + prefetch step k+2 into stage A
            posx = __fadd_rn(posx, sx);
            posy = __fadd_rn(posy, sy);
            posz = __fadd_rn(posz, sz);
            prep_step(vb, posx, posy, posz, stA);
            // consume step k+1 (phantom steps have valid=false; if alpha
            // saturated at step k, this contrib is exactly 0)
            consume(stB, r_out, g_out, b_out, a_out);

            // saturated alpha is exactly 1.0 -> all future contribs 0
            if (a_out >= 1.0f) break;
        }
    }

    long obase = (((long)b * 4) * HH + y) * WW + x;
    const long cstride = (long)HH * WW;
    out[obase + 0 * cstride] = r_out;
    out[obase + 1 * cstride] = g_out;
    out[obase + 2 * cstride] = b_out;
    out[obase + 3 * cstride] = a_out;
}

// ---------------------------------------------------------------------------
// Launch: pipeline the two independent batches across streams.
//   legacy: interleave(b0) -> ev1 -> raymarch(b0)
//   s2:     wait ev1 -> interleave(b1) -> raymarch(b1) -> ev2
//   legacy: wait ev2
// interleave(b1) (LTS-bound) overlaps raymarch(b0) (issue-bound); the two
// raymarch halves co-reside. Batch b's raymarch touches batch (1-b)'s g_vol
// region only through weight-0 clamped neighbor loads; every value that
// region can hold is a finite fp16 pack, and finite*0 contributes exactly 0,
// so the overlap is race-free in output bits.
// ---------------------------------------------------------------------------
extern "C" void kernel_launch(void* const* d_in, const int* in_sizes, int n_in,
                              void* d_out, int out_size) {
    const float* camrot      = (const float*)d_in[0];
    const float* campos      = (const float*)d_in[1];
    const float* focal       = (const float*)d_in[2];
    const float* princpt     = (const float*)d_in[3];
    const float* pixelcoords = (const float*)d_in[4];
    const float* volume      = (const float*)d_in[5];
    float* out = (float*)d_out;

    // One-time handle creation (first call is the uncaptured correctness
    // run, so creation happens outside graph capture; replays reuse).
    static cudaStream_t s2 = nullptr;
    static cudaEvent_t ev1 = nullptr, ev2 = nullptr;
    if (s2 == nullptr) {
        cudaStreamCreateWithFlags(&s2, cudaStreamNonBlocking);
        cudaEventCreateWithFlags(&ev1, cudaEventDisableTiming);
        cudaEventCreateWithFlags(&ev2, cudaEventDisableTiming);
    }

    const int QP = D3 / 4;
    int ithreads = 256;
    int iblocks = (QP + ithreads - 1) / ithreads;
    dim3 rblock(8, 8, 1);
    dim3 rgrid(WW / 8, HH / 8, 1);

    // legacy stream: batch 0
    interleave_kernel<<<iblocks, ithreads>>>((const float4*)volume, 0);
    cudaEventRecord(ev1, 0);
    raymarch_kernel<<<rgrid, rblock>>>(camrot, campos, focal, princpt,
                                       pixelcoords, out, 0);

    // s2: batch 1 (forked after interleave(b0) to keep LTS phases separate)
    cudaStreamWaitEvent(s2, ev1, 0);
    interleave_kernel<<<iblocks, ithreads, 0, s2>>>((const float4*)volume, 1);
    raymarch_kernel<<<rgrid, rblock, 0, s2>>>(camrot, campos, focal, princpt,
                                              pixelcoords, out, 1);
    cudaEventRecord(ev2, s2);

    // join back to the capture-origin stream
    cudaStreamWaitEvent(0, ev2, 0);
}